// round 6
// baseline (speedup 1.0000x reference)
#include <cuda_runtime.h>
#include <math.h>

#define TT   1000
#define BB   512
#define HH   128
#define G4   512
#define KIN  208

typedef unsigned long long u64;

// ---------------- device scratch --------------------------------------------
__device__ float g_pre[(size_t)TT * BB * G4];   // [t][b][512]
__device__ float g_hs0[(size_t)TT * BB * HH];   // [t][b][128]
__device__ float g_Mcomb[42 * 512];
__device__ float g_bias0[512];
__device__ float g_bias1[512];
__device__ float g_peproj[TT * 512];
__device__ float g_last[BB * HH];

// ---------------- f32x2 helpers ---------------------------------------------
#define FFMA2(d, a, b, c) \
    asm("fma.rn.f32x2 %0, %1, %2, %3;" : "=l"(d) : "l"(a), "l"(b), "l"(c))
#define ADDX2(d, a, b) \
    asm("add.rn.f32x2 %0, %1, %2;" : "=l"(d) : "l"(a), "l"(b))
#define PACK2(d, x) \
    asm("mov.b64 %0, {%1, %1};" : "=l"(d) : "r"(__float_as_uint(x)))
#define PACKAB(d, x, y) \
    asm("mov.b64 %0, {%1, %2};" : "=l"(d) : "r"(__float_as_uint(x)), "r"(__float_as_uint(y)))
#define UNPK2(lo, hi, x) \
    asm("mov.b64 {%0, %1}, %2;" : "=r"(lo), "=r"(hi) : "l"(x))

__device__ __forceinline__ float sigf(float x) {
    return __fdividef(1.0f, 1.0f + __expf(-x));
}
__device__ __forceinline__ float tanhfast(float x) {
    float e = __expf(2.0f * x);
    return 1.0f - __fdividef(2.0f, e + 1.0f);
}

// ---------------- weight combine (unchanged) ---------------------------------
__global__ __launch_bounds__(512) void k_comb(
                       const float* __restrict__ Wgcn, const float* __restrict__ bgcn,
                       const float* __restrict__ Wte,  const float* __restrict__ bte,
                       const float* __restrict__ Wih0, const float* __restrict__ bih0,
                       const float* __restrict__ bhh0, const float* __restrict__ bih1,
                       const float* __restrict__ bhh1) {
    int j = threadIdx.x;
    const float* wr = Wih0 + (size_t)j * KIN;
    for (int k = 0; k < 16; k++) {
        float s = 0.f;
        #pragma unroll 4
        for (int d = 0; d < 64; d++) s += Wgcn[k * 64 + d] * (wr[d] + wr[64 + d]);
        g_Mcomb[k * 512 + j] = 0.5f * s;
    }
    for (int k = 0; k < 26; k++) {
        float s = 0.f;
        #pragma unroll 4
        for (int d = 0; d < 64; d++) s += Wte[k * 64 + d] * wr[144 + d];
        g_Mcomb[(16 + k) * 512 + j] = s;
    }
    float b0 = bih0[j] + bhh0[j];
    #pragma unroll 4
    for (int d = 0; d < 64; d++) b0 += bgcn[d] * (wr[d] + wr[64 + d]) + bte[d] * wr[144 + d];
    g_bias0[j] = b0;
    g_bias1[j] = bih1[j] + bhh1[j];
}

// ---------------- positional encoding projection (unchanged) -----------------
__global__ __launch_bounds__(256) void k_pe(const float* __restrict__ Wih0) {
    int id = blockIdx.x * blockDim.x + threadIdx.x;
    if (id >= TT * 512) return;
    int t = id >> 9, j = id & 511;
    const float* wr = Wih0 + (size_t)j * KIN + 128;
    float acc = 0.f;
    #pragma unroll
    for (int i = 0; i < 8; i++) {
        float div = expf(-(float)(2 * i) * (9.210340371976184f / 16.0f));
        float ang = (float)t * div;
        acc += sinf(ang) * wr[2 * i] + cosf(ang) * wr[2 * i + 1];
    }
    g_peproj[id] = acc;
}

// ---------------- pre0 (unchanged from R4, passing) --------------------------
__global__ __launch_bounds__(256) void k_pre0(const float* __restrict__ xs,
                                              const float* __restrict__ xt) {
    extern __shared__ float sm[];
    float* Msm = sm;               // [42][512]
    float* xT  = sm + 42 * 512;    // [42][8]
    int t = blockIdx.x, tid = threadIdx.x;
    int j0 = tid * 2;
    for (int i = tid; i < 42 * 512; i += 256) Msm[i] = g_Mcomb[i];
    u64 bj0, bj1;
    PACK2(bj0, g_bias0[j0]     + g_peproj[t * 512 + j0]);
    PACK2(bj1, g_bias0[j0 + 1] + g_peproj[t * 512 + j0 + 1]);
    __syncthreads();
    for (int bt = 0; bt < 64; bt++) {
        int bb = bt * 8;
        #pragma unroll
        for (int s = 0; s < 2; s++) {
            int i = tid + s * 256;
            if (i < 128) {
                int b = i >> 4, k = i & 15;
                const float* xp = xs + ((size_t)(bb + b) * TT + t) * 32;
                xT[k * 8 + b] = xp[k] + xp[k + 16];
            } else if (i < 336) {
                int idx = i - 128; int b = idx / 26, k = idx - b * 26;
                xT[(16 + k) * 8 + b] = xt[((size_t)(bb + b) * TT + t) * 26 + k];
            }
        }
        __syncthreads();
        u64 A[8];
        A[0] = bj0; A[1] = bj0; A[2] = bj0; A[3] = bj0;
        A[4] = bj1; A[5] = bj1; A[6] = bj1; A[7] = bj1;
        #pragma unroll 6
        for (int k = 0; k < 42; k++) {
            float2 w = *(const float2*)(Msm + k * 512 + j0);
            u64 wa, wb; PACK2(wa, w.x); PACK2(wb, w.y);
            ulonglong2 h0 = *(const ulonglong2*)(xT + k * 8);
            ulonglong2 h1 = *(const ulonglong2*)(xT + k * 8 + 4);
            FFMA2(A[0], wa, h0.x, A[0]); FFMA2(A[1], wa, h0.y, A[1]);
            FFMA2(A[2], wa, h1.x, A[2]); FFMA2(A[3], wa, h1.y, A[3]);
            FFMA2(A[4], wb, h0.x, A[4]); FFMA2(A[5], wb, h0.y, A[5]);
            FFMA2(A[6], wb, h1.x, A[6]); FFMA2(A[7], wb, h1.y, A[7]);
        }
        unsigned zj0[8], zj1[8];
        UNPK2(zj0[0], zj0[1], A[0]); UNPK2(zj0[2], zj0[3], A[1]);
        UNPK2(zj0[4], zj0[5], A[2]); UNPK2(zj0[6], zj0[7], A[3]);
        UNPK2(zj1[0], zj1[1], A[4]); UNPK2(zj1[2], zj1[3], A[5]);
        UNPK2(zj1[4], zj1[5], A[6]); UNPK2(zj1[6], zj1[7], A[7]);
        size_t po = ((size_t)t * BB + bb) * G4 + j0;
        #pragma unroll
        for (int b = 0; b < 8; b++)
            *(float2*)(g_pre + po + (size_t)b * G4) =
                make_float2(__uint_as_float(zj0[b]), __uint_as_float(zj1[b]));
        __syncthreads();
    }
}

// ---------------- pre1 (unchanged from R4, passing) --------------------------
__global__ __launch_bounds__(256) void k_pre1(const float* __restrict__ Wih1) {
    extern __shared__ float sm[];
    float* Wsm = sm;               // [96][512]
    float* hT8 = sm + 96 * 512;    // [128][8]
    int t = blockIdx.x, tid = threadIdx.x;
    int j0 = tid * 2;
    u64 w00[32], w11[32];
    #pragma unroll
    for (int k = 0; k < 32; k++) {
        PACK2(w00[k], Wih1[(size_t)j0 * HH + k]);
        PACK2(w11[k], Wih1[(size_t)(j0 + 1) * HH + k]);
    }
    for (int i = tid; i < 96 * 512; i += 256) {
        int kk = i >> 9, jj = i & 511;
        Wsm[i] = Wih1[(size_t)jj * HH + 32 + kk];
    }
    u64 bj0, bj1;
    PACK2(bj0, g_bias1[j0]);
    PACK2(bj1, g_bias1[j0 + 1]);
    __syncthreads();
    for (int bt = 0; bt < 64; bt++) {
        int bb = bt * 8;
        #pragma unroll
        for (int s = 0; s < 4; s++) {
            int i = tid + s * 256;
            int b = i >> 7, k = i & 127;
            hT8[k * 8 + b] = g_hs0[((size_t)t * BB + bb + b) * HH + k];
        }
        __syncthreads();
        u64 A[8];
        A[0] = bj0; A[1] = bj0; A[2] = bj0; A[3] = bj0;
        A[4] = bj1; A[5] = bj1; A[6] = bj1; A[7] = bj1;
        #pragma unroll
        for (int k = 0; k < 32; k++) {
            ulonglong2 h0 = *(const ulonglong2*)(hT8 + k * 8);
            ulonglong2 h1 = *(const ulonglong2*)(hT8 + k * 8 + 4);
            FFMA2(A[0], w00[k], h0.x, A[0]); FFMA2(A[1], w00[k], h0.y, A[1]);
            FFMA2(A[2], w00[k], h1.x, A[2]); FFMA2(A[3], w00[k], h1.y, A[3]);
            FFMA2(A[4], w11[k], h0.x, A[4]); FFMA2(A[5], w11[k], h0.y, A[5]);
            FFMA2(A[6], w11[k], h1.x, A[6]); FFMA2(A[7], w11[k], h1.y, A[7]);
        }
        #pragma unroll 4
        for (int k = 32; k < 128; k++) {
            float2 w = *(const float2*)(Wsm + (k - 32) * 512 + j0);
            u64 wa, wb; PACK2(wa, w.x); PACK2(wb, w.y);
            ulonglong2 h0 = *(const ulonglong2*)(hT8 + k * 8);
            ulonglong2 h1 = *(const ulonglong2*)(hT8 + k * 8 + 4);
            FFMA2(A[0], wa, h0.x, A[0]); FFMA2(A[1], wa, h0.y, A[1]);
            FFMA2(A[2], wa, h1.x, A[2]); FFMA2(A[3], wa, h1.y, A[3]);
            FFMA2(A[4], wb, h0.x, A[4]); FFMA2(A[5], wb, h0.y, A[5]);
            FFMA2(A[6], wb, h1.x, A[6]); FFMA2(A[7], wb, h1.y, A[7]);
        }
        unsigned zj0[8], zj1[8];
        UNPK2(zj0[0], zj0[1], A[0]); UNPK2(zj0[2], zj0[3], A[1]);
        UNPK2(zj0[4], zj0[5], A[2]); UNPK2(zj0[6], zj0[7], A[3]);
        UNPK2(zj1[0], zj1[1], A[4]); UNPK2(zj1[2], zj1[3], A[5]);
        UNPK2(zj1[4], zj1[5], A[6]); UNPK2(zj1[6], zj1[7], A[7]);
        size_t po = ((size_t)t * BB + bb) * G4 + j0;
        #pragma unroll
        for (int b = 0; b < 8; b++)
            *(float2*)(g_pre + po + (size_t)b * G4) =
                make_float2(__uint_as_float(zj0[b]), __uint_as_float(zj1[b]));
        __syncthreads();
    }
}

// ---------------- LSTM sweep: 512 thr, k-split halves, j-packed f32x2 --------
// 128 CTAs x 4 batch rows. Thread: half = tid>>8 owns k-range [half*64, half*64+64),
// jj = tid&255, gate rows j0=2*jj, j0+1. Accums A_b = (z[j0][b], z[j1][b]).
// Weights: 32 k-rows in regs (j-paired u64), 32 k-rows in SMEM (natural LDS.64).
// h kept duplicated in SMEM: hTd[k][b] = (h,h) u64 -> broadcast LDS.128 feeds FFMA2.
__global__ __launch_bounds__(512) void k_lstm(const float* __restrict__ Whh,
                                              int write_hs, int write_last) {
    extern __shared__ float sm[];
    float* Wsm = sm;                          // [64][512]: rows 0-31 k=32..63, 32-63 k=96..127
    float* zbf = sm + 64 * 512;               // [4][520] z (j-major per batch row)
    u64*   pex = (u64*)(sm + 64 * 512 + 4 * 520);   // [4][260] partial exchange
    u64*   hTd = (u64*)(sm + 64 * 512 + 4 * 520 + 4 * 260 * 2); // [128][4] dup-h

    int tid  = threadIdx.x;
    int half = tid >> 8;                      // 0: k<64, 1: k>=64
    int jj   = tid & 255;
    int j0   = jj * 2;
    int bb   = blockIdx.x * 4;
    int kbase = half * 64;

    // register-resident weights: k = kbase..kbase+31, j-paired
    u64 wreg[32];
    #pragma unroll
    for (int k = 0; k < 32; k++) {
        int kk = kbase + k;
        PACKAB(wreg[k], Whh[(size_t)j0 * HH + kk], Whh[(size_t)(j0 + 1) * HH + kk]);
    }
    // SMEM weights: rows (half*32 + r) <- global k = kbase + 32 + r
    for (int i = tid; i < 64 * 512; i += 512) {
        int r = i >> 9, j = i & 511;
        int kg = (r < 32) ? (32 + r) : (96 + (r - 32));
        Wsm[i] = Whh[(size_t)j * HH + kg];
    }
    if (tid < 512) hTd[tid] = 0ull;           // 128*4 entries

    int u0 = tid & 127, bq = tid >> 7;        // gate assignment: one (u,b) per thread
    float c = 0.f, hlast = 0.f;
    const float* WsmHalf = Wsm + (half * 32) * 512;
    const u64*   hTdHalf = hTd + kbase * 4;
    __syncthreads();

    for (int t = 0; t < TT; t++) {
        // prefetch this step's pre-activations for the two batch rows we finalize
        int bA = half * 2, bB = bA + 1;
        size_t poA = ((size_t)t * BB + bb + bA) * G4 + j0;
        u64 qA = *(const u64*)(g_pre + poA);
        u64 qB = *(const u64*)(g_pre + poA + G4);

        u64 A0 = 0, A1 = 0, A2 = 0, A3 = 0;   // partial z over our k-range, per batch row
        #pragma unroll
        for (int k = 0; k < 32; k++) {
            ulonglong2 h01 = *(const ulonglong2*)(hTdHalf + k * 4);
            ulonglong2 h23 = *(const ulonglong2*)(hTdHalf + k * 4 + 2);
            FFMA2(A0, wreg[k], h01.x, A0);
            FFMA2(A1, wreg[k], h01.y, A1);
            FFMA2(A2, wreg[k], h23.x, A2);
            FFMA2(A3, wreg[k], h23.y, A3);
        }
        #pragma unroll 8
        for (int k = 0; k < 32; k++) {
            u64 w = *(const u64*)(WsmHalf + k * 512 + j0);
            ulonglong2 h01 = *(const ulonglong2*)(hTdHalf + (32 + k) * 4);
            ulonglong2 h23 = *(const ulonglong2*)(hTdHalf + (32 + k) * 4 + 2);
            FFMA2(A0, w, h01.x, A0);
            FFMA2(A1, w, h01.y, A1);
            FFMA2(A2, w, h23.x, A2);
            FFMA2(A3, w, h23.y, A3);
        }
        // exchange partials for the two batch rows the OTHER half finalizes
        if (half == 0) {
            pex[2 * 260 + jj] = A2;
            pex[3 * 260 + jj] = A3;
        } else {
            pex[0 * 260 + jj] = A0;
            pex[1 * 260 + jj] = A1;
        }
        __syncthreads();
        {
            u64 pA, pB, zA, zB;
            if (half == 0) { pA = pex[0 * 260 + jj]; pB = pex[1 * 260 + jj];
                             zA = A0; zB = A1; }
            else           { pA = pex[2 * 260 + jj]; pB = pex[3 * 260 + jj];
                             zA = A2; zB = A3; }
            ADDX2(zA, zA, pA); ADDX2(zB, zB, pB);
            ADDX2(zA, zA, qA); ADDX2(zB, zB, qB);
            *(u64*)(zbf + bA * 520 + j0) = zA;
            *(u64*)(zbf + bB * 520 + j0) = zB;
        }
        __syncthreads();

        // gate phase: one (u,b) per thread
        float zi = zbf[bq * 520 + u0];
        float zf = zbf[bq * 520 + u0 + 128];
        float zg = zbf[bq * 520 + u0 + 256];
        float zo = zbf[bq * 520 + u0 + 384];
        c = sigf(zf) * c + sigf(zi) * tanhfast(zg);
        float h = sigf(zo) * tanhfast(c);
        hlast = h;
        u64 hd; PACK2(hd, h);
        hTd[u0 * 4 + bq] = hd;
        if (write_hs) g_hs0[((size_t)t * BB + bb + bq) * HH + u0] = h;
        __syncthreads();
    }
    if (write_last) g_last[(bb + bq) * HH + u0] = hlast;
}

// ---------------- MLP head (unchanged) ---------------------------------------
__global__ __launch_bounds__(128) void k_head(
                       const float* __restrict__ W1, const float* __restrict__ b1,
                       const float* __restrict__ W2, const float* __restrict__ b2,
                       const float* __restrict__ W3, const float* __restrict__ b3,
                       float* __restrict__ out) {
    __shared__ float xin[128], y1[128], y2[64];
    int b = blockIdx.x, j = threadIdx.x;
    xin[j] = g_last[b * HH + j];
    __syncthreads();
    float s = b1[j];
    #pragma unroll 4
    for (int k = 0; k < 128; k++) s += xin[k] * W1[j * 128 + k];
    y1[j] = fmaxf(s, 0.f);
    __syncthreads();
    if (j < 64) {
        float s2 = b2[j];
        #pragma unroll 4
        for (int k = 0; k < 128; k++) s2 += y1[k] * W2[j * 128 + k];
        y2[j] = fmaxf(s2, 0.f);
    }
    __syncthreads();
    if (j < 26) {
        float s3 = b3[j];
        #pragma unroll 4
        for (int k = 0; k < 64; k++) s3 += y2[k] * W3[j * 64 + k];
        out[b * 26 + j] = s3;
    }
}

// ---------------- launch -----------------------------------------------------
extern "C" void kernel_launch(void* const* d_in, const int* in_sizes, int n_in,
                              void* d_out, int out_size) {
    const float* xs   = (const float*)d_in[0];
    const float* xt   = (const float*)d_in[1];
    const float* Wgcn = (const float*)d_in[2];
    const float* bgcn = (const float*)d_in[3];
    const float* Wte  = (const float*)d_in[4];
    const float* bte  = (const float*)d_in[5];
    const float* Wih0 = (const float*)d_in[6];
    const float* Whh0 = (const float*)d_in[7];
    const float* bih0 = (const float*)d_in[8];
    const float* bhh0 = (const float*)d_in[9];
    const float* Wih1 = (const float*)d_in[10];
    const float* Whh1 = (const float*)d_in[11];
    const float* bih1 = (const float*)d_in[12];
    const float* bhh1 = (const float*)d_in[13];
    const float* W1   = (const float*)d_in[14];
    const float* b1   = (const float*)d_in[15];
    const float* W2   = (const float*)d_in[16];
    const float* b2   = (const float*)d_in[17];
    const float* W3   = (const float*)d_in[18];
    const float* b3   = (const float*)d_in[19];

    const int SM_PRE0 = (42 * 512 + 42 * 8) * 4;                        //  87,360 B
    const int SM_PRE1 = (96 * 512 + 128 * 8) * 4;                       // 200,704 B
    const int SM_LSTM = (64 * 512 + 4 * 520 + 4 * 260 * 2 + 128 * 4 * 2) * 4; // 151,808 B
    cudaFuncSetAttribute(k_pre0, cudaFuncAttributeMaxDynamicSharedMemorySize, SM_PRE0);
    cudaFuncSetAttribute(k_pre1, cudaFuncAttributeMaxDynamicSharedMemorySize, SM_PRE1);
    cudaFuncSetAttribute(k_lstm, cudaFuncAttributeMaxDynamicSharedMemorySize, SM_LSTM);

    k_comb<<<1, 512>>>(Wgcn, bgcn, Wte, bte, Wih0, bih0, bhh0, bih1, bhh1);
    k_pe<<<(TT * 512 + 255) / 256, 256>>>(Wih0);
    k_pre0<<<TT, 256, SM_PRE0>>>(xs, xt);
    k_lstm<<<BB / 4, 512, SM_LSTM>>>(Whh0, 1, 0);   // layer 0 -> hs0
    k_pre1<<<TT, 256, SM_PRE1>>>(Wih1);             // g_pre := pre1
    k_lstm<<<BB / 4, 512, SM_LSTM>>>(Whh1, 0, 1);   // layer 1 -> last
    k_head<<<BB, 128>>>(W1, b1, W2, b2, W3, b3, (float*)d_out);
}

// round 7
// speedup vs baseline: 1.2205x; 1.2205x over previous
#include <cuda_runtime.h>
#include <math.h>

#define TT   1000
#define BB   512
#define HH   128
#define G4   512
#define KIN  208
#define KREG 48               // k-rows in registers (per thread: 2*KREG u64)
#define KSM  (HH - KREG)      // 80 k-rows in SMEM

typedef unsigned long long u64;

// ---------------- device scratch --------------------------------------------
__device__ float g_pre[(size_t)TT * BB * G4];   // [t][b][512]
__device__ float g_hs0[(size_t)TT * BB * HH];   // [t][b][128]
__device__ float g_Mcomb[42 * 512];
__device__ float g_bias0[512];
__device__ float g_bias1[512];
__device__ float g_peproj[TT * 512];
__device__ float g_last[BB * HH];

// ---------------- f32x2 helpers ---------------------------------------------
#define FFMA2(d, a, b, c) \
    asm("fma.rn.f32x2 %0, %1, %2, %3;" : "=l"(d) : "l"(a), "l"(b), "l"(c))
#define PACK2(d, x) \
    asm("mov.b64 %0, {%1, %1};" : "=l"(d) : "r"(__float_as_uint(x)))
#define UNPK2(lo, hi, x) \
    asm("mov.b64 {%0, %1}, %2;" : "=r"(lo), "=r"(hi) : "l"(x))

__device__ __forceinline__ float sigf(float x) {
    return __fdividef(1.0f, 1.0f + __expf(-x));
}
__device__ __forceinline__ float tanhfast(float x) {
    float e = __expf(2.0f * x);
    return 1.0f - __fdividef(2.0f, e + 1.0f);
}

// ---------------- weight combine (unchanged, passing) ------------------------
__global__ __launch_bounds__(512) void k_comb(
                       const float* __restrict__ Wgcn, const float* __restrict__ bgcn,
                       const float* __restrict__ Wte,  const float* __restrict__ bte,
                       const float* __restrict__ Wih0, const float* __restrict__ bih0,
                       const float* __restrict__ bhh0, const float* __restrict__ bih1,
                       const float* __restrict__ bhh1) {
    int j = threadIdx.x;
    const float* wr = Wih0 + (size_t)j * KIN;
    for (int k = 0; k < 16; k++) {
        float s = 0.f;
        #pragma unroll 4
        for (int d = 0; d < 64; d++) s += Wgcn[k * 64 + d] * (wr[d] + wr[64 + d]);
        g_Mcomb[k * 512 + j] = 0.5f * s;
    }
    for (int k = 0; k < 26; k++) {
        float s = 0.f;
        #pragma unroll 4
        for (int d = 0; d < 64; d++) s += Wte[k * 64 + d] * wr[144 + d];
        g_Mcomb[(16 + k) * 512 + j] = s;
    }
    float b0 = bih0[j] + bhh0[j];
    #pragma unroll 4
    for (int d = 0; d < 64; d++) b0 += bgcn[d] * (wr[d] + wr[64 + d]) + bte[d] * wr[144 + d];
    g_bias0[j] = b0;
    g_bias1[j] = bih1[j] + bhh1[j];
}

// ---------------- positional encoding projection (unchanged) -----------------
__global__ __launch_bounds__(256) void k_pe(const float* __restrict__ Wih0) {
    int id = blockIdx.x * blockDim.x + threadIdx.x;
    if (id >= TT * 512) return;
    int t = id >> 9, j = id & 511;
    const float* wr = Wih0 + (size_t)j * KIN + 128;
    float acc = 0.f;
    #pragma unroll
    for (int i = 0; i < 8; i++) {
        float div = expf(-(float)(2 * i) * (9.210340371976184f / 16.0f));
        float ang = (float)t * div;
        acc += sinf(ang) * wr[2 * i] + cosf(ang) * wr[2 * i + 1];
    }
    g_peproj[id] = acc;
}

// ---------------- pre0 (unchanged from R4, passing) --------------------------
__global__ __launch_bounds__(256, 1) void k_pre0(const float* __restrict__ xs,
                                                 const float* __restrict__ xt) {
    extern __shared__ float sm[];
    float* Msm = sm;               // [42][512]
    float* xT  = sm + 42 * 512;    // [42][8]
    int t = blockIdx.x, tid = threadIdx.x;
    int j0 = tid * 2;
    for (int i = tid; i < 42 * 512; i += 256) Msm[i] = g_Mcomb[i];
    u64 bj0, bj1;
    PACK2(bj0, g_bias0[j0]     + g_peproj[t * 512 + j0]);
    PACK2(bj1, g_bias0[j0 + 1] + g_peproj[t * 512 + j0 + 1]);
    __syncthreads();
    for (int bt = 0; bt < 64; bt++) {
        int bb = bt * 8;
        #pragma unroll
        for (int s = 0; s < 2; s++) {
            int i = tid + s * 256;
            if (i < 128) {
                int b = i >> 4, k = i & 15;
                const float* xp = xs + ((size_t)(bb + b) * TT + t) * 32;
                xT[k * 8 + b] = xp[k] + xp[k + 16];
            } else if (i < 336) {
                int idx = i - 128; int b = idx / 26, k = idx - b * 26;
                xT[(16 + k) * 8 + b] = xt[((size_t)(bb + b) * TT + t) * 26 + k];
            }
        }
        __syncthreads();
        u64 A[8];
        A[0] = bj0; A[1] = bj0; A[2] = bj0; A[3] = bj0;
        A[4] = bj1; A[5] = bj1; A[6] = bj1; A[7] = bj1;
        #pragma unroll 6
        for (int k = 0; k < 42; k++) {
            float2 w = *(const float2*)(Msm + k * 512 + j0);
            u64 wa, wb; PACK2(wa, w.x); PACK2(wb, w.y);
            ulonglong2 h0 = *(const ulonglong2*)(xT + k * 8);
            ulonglong2 h1 = *(const ulonglong2*)(xT + k * 8 + 4);
            FFMA2(A[0], wa, h0.x, A[0]); FFMA2(A[1], wa, h0.y, A[1]);
            FFMA2(A[2], wa, h1.x, A[2]); FFMA2(A[3], wa, h1.y, A[3]);
            FFMA2(A[4], wb, h0.x, A[4]); FFMA2(A[5], wb, h0.y, A[5]);
            FFMA2(A[6], wb, h1.x, A[6]); FFMA2(A[7], wb, h1.y, A[7]);
        }
        unsigned zj0[8], zj1[8];
        UNPK2(zj0[0], zj0[1], A[0]); UNPK2(zj0[2], zj0[3], A[1]);
        UNPK2(zj0[4], zj0[5], A[2]); UNPK2(zj0[6], zj0[7], A[3]);
        UNPK2(zj1[0], zj1[1], A[4]); UNPK2(zj1[2], zj1[3], A[5]);
        UNPK2(zj1[4], zj1[5], A[6]); UNPK2(zj1[6], zj1[7], A[7]);
        size_t po = ((size_t)t * BB + bb) * G4 + j0;
        #pragma unroll
        for (int b = 0; b < 8; b++)
            *(float2*)(g_pre + po + (size_t)b * G4) =
                make_float2(__uint_as_float(zj0[b]), __uint_as_float(zj1[b]));
        __syncthreads();
    }
}

// ---------------- pre1: g_pre = hs0 @ Wih1^T + bias1 (48 reg-rows) -----------
__global__ __launch_bounds__(256, 1) void k_pre1(const float* __restrict__ Wih1) {
    extern __shared__ float sm[];
    float* Wsm = sm;               // [KSM][512]  rows KREG..127 of Wih1^T
    float* hT8 = sm + KSM * 512;   // [128][8]
    int t = blockIdx.x, tid = threadIdx.x;
    int j0 = tid * 2;
    u64 w00[KREG], w11[KREG];
    #pragma unroll
    for (int k = 0; k < KREG; k++) {
        PACK2(w00[k], Wih1[(size_t)j0 * HH + k]);
        PACK2(w11[k], Wih1[(size_t)(j0 + 1) * HH + k]);
    }
    for (int i = tid; i < KSM * 512; i += 256) {
        int kk = i >> 9, jj = i & 511;
        Wsm[i] = Wih1[(size_t)jj * HH + KREG + kk];
    }
    u64 bj0, bj1;
    PACK2(bj0, g_bias1[j0]);
    PACK2(bj1, g_bias1[j0 + 1]);
    __syncthreads();
    for (int bt = 0; bt < 64; bt++) {
        int bb = bt * 8;
        #pragma unroll
        for (int s = 0; s < 4; s++) {
            int i = tid + s * 256;
            int b = i >> 7, k = i & 127;
            hT8[k * 8 + b] = g_hs0[((size_t)t * BB + bb + b) * HH + k];
        }
        __syncthreads();
        u64 A[8];
        A[0] = bj0; A[1] = bj0; A[2] = bj0; A[3] = bj0;
        A[4] = bj1; A[5] = bj1; A[6] = bj1; A[7] = bj1;
        #pragma unroll
        for (int k = 0; k < KREG; k++) {
            ulonglong2 h0 = *(const ulonglong2*)(hT8 + k * 8);
            ulonglong2 h1 = *(const ulonglong2*)(hT8 + k * 8 + 4);
            FFMA2(A[0], w00[k], h0.x, A[0]); FFMA2(A[1], w00[k], h0.y, A[1]);
            FFMA2(A[2], w00[k], h1.x, A[2]); FFMA2(A[3], w00[k], h1.y, A[3]);
            FFMA2(A[4], w11[k], h0.x, A[4]); FFMA2(A[5], w11[k], h0.y, A[5]);
            FFMA2(A[6], w11[k], h1.x, A[6]); FFMA2(A[7], w11[k], h1.y, A[7]);
        }
        #pragma unroll 4
        for (int k = KREG; k < 128; k++) {
            float2 w = *(const float2*)(Wsm + (k - KREG) * 512 + j0);
            u64 wa, wb; PACK2(wa, w.x); PACK2(wb, w.y);
            ulonglong2 h0 = *(const ulonglong2*)(hT8 + k * 8);
            ulonglong2 h1 = *(const ulonglong2*)(hT8 + k * 8 + 4);
            FFMA2(A[0], wa, h0.x, A[0]); FFMA2(A[1], wa, h0.y, A[1]);
            FFMA2(A[2], wa, h1.x, A[2]); FFMA2(A[3], wa, h1.y, A[3]);
            FFMA2(A[4], wb, h0.x, A[4]); FFMA2(A[5], wb, h0.y, A[5]);
            FFMA2(A[6], wb, h1.x, A[6]); FFMA2(A[7], wb, h1.y, A[7]);
        }
        unsigned zj0[8], zj1[8];
        UNPK2(zj0[0], zj0[1], A[0]); UNPK2(zj0[2], zj0[3], A[1]);
        UNPK2(zj0[4], zj0[5], A[2]); UNPK2(zj0[6], zj0[7], A[3]);
        UNPK2(zj1[0], zj1[1], A[4]); UNPK2(zj1[2], zj1[3], A[5]);
        UNPK2(zj1[4], zj1[5], A[6]); UNPK2(zj1[6], zj1[7], A[7]);
        size_t po = ((size_t)t * BB + bb) * G4 + j0;
        #pragma unroll
        for (int b = 0; b < 8; b++)
            *(float2*)(g_pre + po + (size_t)b * G4) =
                make_float2(__uint_as_float(zj0[b]), __uint_as_float(zj1[b]));
        __syncthreads();
    }
}

// ---------------- LSTM sweep (R4 structure, true-RF weights, 48 rows) --------
// 128 CTAs x 4 batch rows, 256 threads. Thread owns gate rows j0=2t, j0+1.
// z accums batch-packed: A00=(z[j0][b0],z[j0][b1]) etc. One LDS.128 per k for h.
__global__ __launch_bounds__(256, 1) void k_lstm(const float* __restrict__ Whh,
                                                 int write_hs, int write_last) {
    extern __shared__ float sm[];
    float* Wsm = sm;                 // [KSM][512]
    float* zb  = sm + KSM * 512;     // [4][516] z by batch row (padded)
    float* hT  = zb + 4 * 516;       // [128][4]
    int tid = threadIdx.x;
    int j0 = tid * 2;
    int bb = blockIdx.x * 4;
    u64 w00[KREG], w11[KREG];
    #pragma unroll
    for (int k = 0; k < KREG; k++) {
        PACK2(w00[k], Whh[(size_t)j0 * HH + k]);
        PACK2(w11[k], Whh[(size_t)(j0 + 1) * HH + k]);
    }
    for (int i = tid; i < KSM * 512; i += 256) {
        int kk = i >> 9, jj = i & 511;
        Wsm[i] = Whh[(size_t)jj * HH + KREG + kk];
    }
    hT[tid] = 0.f; hT[tid + 256] = 0.f;
    int u0 = tid & 127, b0 = tid >> 7;   // id0 = tid
    int b1 = b0 + 2;                     // id1 = tid + 256 (same u0)
    float c0 = 0.f, c1 = 0.f, hl0 = 0.f, hl1 = 0.f;
    __syncthreads();

    for (int t = 0; t < TT; t++) {
        size_t po = ((size_t)t * BB + bb) * G4 + j0;
        float2 q0 = *(const float2*)(g_pre + po);             // (p[j0][b], p[j1][b])
        float2 q1 = *(const float2*)(g_pre + po + G4);
        float2 q2 = *(const float2*)(g_pre + po + 2 * G4);
        float2 q3 = *(const float2*)(g_pre + po + 3 * G4);

        u64 A00 = 0, A01 = 0, A10 = 0, A11 = 0;
        #pragma unroll
        for (int k = 0; k < KREG; k++) {
            ulonglong2 hv = *(const ulonglong2*)(hT + k * 4);
            FFMA2(A00, w00[k], hv.x, A00);
            FFMA2(A01, w00[k], hv.y, A01);
            FFMA2(A10, w11[k], hv.x, A10);
            FFMA2(A11, w11[k], hv.y, A11);
        }
        #pragma unroll 8
        for (int k = KREG; k < 128; k++) {
            float2 w = *(const float2*)(Wsm + (k - KREG) * 512 + j0);
            u64 wa, wb; PACK2(wa, w.x); PACK2(wb, w.y);
            ulonglong2 hv = *(const ulonglong2*)(hT + k * 4);
            FFMA2(A00, wa, hv.x, A00);
            FFMA2(A01, wa, hv.y, A01);
            FFMA2(A10, wb, hv.x, A10);
            FFMA2(A11, wb, hv.y, A11);
        }
        unsigned a00l, a00h, a01l, a01h, a10l, a10h, a11l, a11h;
        UNPK2(a00l, a00h, A00); UNPK2(a01l, a01h, A01);
        UNPK2(a10l, a10h, A10); UNPK2(a11l, a11h, A11);
        *(float2*)(zb + 0 * 516 + j0) =
            make_float2(__uint_as_float(a00l) + q0.x, __uint_as_float(a10l) + q0.y);
        *(float2*)(zb + 1 * 516 + j0) =
            make_float2(__uint_as_float(a00h) + q1.x, __uint_as_float(a10h) + q1.y);
        *(float2*)(zb + 2 * 516 + j0) =
            make_float2(__uint_as_float(a01l) + q2.x, __uint_as_float(a11l) + q2.y);
        *(float2*)(zb + 3 * 516 + j0) =
            make_float2(__uint_as_float(a01h) + q3.x, __uint_as_float(a11h) + q3.y);
        __syncthreads();

        float zi0 = zb[b0 * 516 + u0];
        float zf0 = zb[b0 * 516 + u0 + 128];
        float zg0 = zb[b0 * 516 + u0 + 256];
        float zo0 = zb[b0 * 516 + u0 + 384];
        c0 = sigf(zf0) * c0 + sigf(zi0) * tanhfast(zg0);
        float h0v = sigf(zo0) * tanhfast(c0);
        float zi1 = zb[b1 * 516 + u0];
        float zf1 = zb[b1 * 516 + u0 + 128];
        float zg1 = zb[b1 * 516 + u0 + 256];
        float zo1 = zb[b1 * 516 + u0 + 384];
        c1 = sigf(zf1) * c1 + sigf(zi1) * tanhfast(zg1);
        float h1v = sigf(zo1) * tanhfast(c1);
        hl0 = h0v; hl1 = h1v;
        hT[u0 * 4 + b0] = h0v;
        hT[u0 * 4 + b1] = h1v;
        if (write_hs) {
            g_hs0[((size_t)t * BB + bb + b0) * HH + u0] = h0v;
            g_hs0[((size_t)t * BB + bb + b1) * HH + u0] = h1v;
        }
        __syncthreads();
    }
    if (write_last) {
        g_last[(bb + b0) * HH + u0] = hl0;
        g_last[(bb + b1) * HH + u0] = hl1;
    }
}

// ---------------- MLP head (unchanged) ---------------------------------------
__global__ __launch_bounds__(128) void k_head(
                       const float* __restrict__ W1, const float* __restrict__ b1,
                       const float* __restrict__ W2, const float* __restrict__ b2,
                       const float* __restrict__ W3, const float* __restrict__ b3,
                       float* __restrict__ out) {
    __shared__ float xin[128], y1[128], y2[64];
    int b = blockIdx.x, j = threadIdx.x;
    xin[j] = g_last[b * HH + j];
    __syncthreads();
    float s = b1[j];
    #pragma unroll 4
    for (int k = 0; k < 128; k++) s += xin[k] * W1[j * 128 + k];
    y1[j] = fmaxf(s, 0.f);
    __syncthreads();
    if (j < 64) {
        float s2 = b2[j];
        #pragma unroll 4
        for (int k = 0; k < 128; k++) s2 += y1[k] * W2[j * 128 + k];
        y2[j] = fmaxf(s2, 0.f);
    }
    __syncthreads();
    if (j < 26) {
        float s3 = b3[j];
        #pragma unroll 4
        for (int k = 0; k < 64; k++) s3 += y2[k] * W3[j * 64 + k];
        out[b * 26 + j] = s3;
    }
}

// ---------------- launch -----------------------------------------------------
extern "C" void kernel_launch(void* const* d_in, const int* in_sizes, int n_in,
                              void* d_out, int out_size) {
    const float* xs   = (const float*)d_in[0];
    const float* xt   = (const float*)d_in[1];
    const float* Wgcn = (const float*)d_in[2];
    const float* bgcn = (const float*)d_in[3];
    const float* Wte  = (const float*)d_in[4];
    const float* bte  = (const float*)d_in[5];
    const float* Wih0 = (const float*)d_in[6];
    const float* Whh0 = (const float*)d_in[7];
    const float* bih0 = (const float*)d_in[8];
    const float* bhh0 = (const float*)d_in[9];
    const float* Wih1 = (const float*)d_in[10];
    const float* Whh1 = (const float*)d_in[11];
    const float* bih1 = (const float*)d_in[12];
    const float* bhh1 = (const float*)d_in[13];
    const float* W1   = (const float*)d_in[14];
    const float* b1   = (const float*)d_in[15];
    const float* W2   = (const float*)d_in[16];
    const float* b2   = (const float*)d_in[17];
    const float* W3   = (const float*)d_in[18];
    const float* b3   = (const float*)d_in[19];

    const int SM_PRE0 = (42 * 512 + 42 * 8) * 4;                  //  87,360 B
    const int SM_PRE1 = (KSM * 512 + 128 * 8) * 4;                // 167,936 B
    const int SM_LSTM = (KSM * 512 + 4 * 516 + 128 * 4) * 4;      // 174,144 B
    cudaFuncSetAttribute(k_pre0, cudaFuncAttributeMaxDynamicSharedMemorySize, SM_PRE0);
    cudaFuncSetAttribute(k_pre1, cudaFuncAttributeMaxDynamicSharedMemorySize, SM_PRE1);
    cudaFuncSetAttribute(k_lstm, cudaFuncAttributeMaxDynamicSharedMemorySize, SM_LSTM);

    k_comb<<<1, 512>>>(Wgcn, bgcn, Wte, bte, Wih0, bih0, bhh0, bih1, bhh1);
    k_pe<<<(TT * 512 + 255) / 256, 256>>>(Wih0);
    k_pre0<<<TT, 256, SM_PRE0>>>(xs, xt);
    k_lstm<<<BB / 4, 256, SM_LSTM>>>(Whh0, 1, 0);   // layer 0 -> hs0
    k_pre1<<<TT, 256, SM_PRE1>>>(Wih1);             // g_pre := pre1
    k_lstm<<<BB / 4, 256, SM_LSTM>>>(Whh1, 0, 1);   // layer 1 -> last
    k_head<<<BB, 128>>>(W1, b1, W2, b2, W3, b3, (float*)d_out);
}

// round 12
// speedup vs baseline: 1.5396x; 1.2614x over previous
#include <cuda_runtime.h>
#include <cuda_fp16.h>
#include <cstdint>
#include <cstddef>
#include <math.h>

#define TT   1000
#define BB   512
#define HH   128
#define G4   512
#define KIN  208
#define KREG 48               // pre1: k-rows in registers
#define KSM  (HH - KREG)      // pre1: 80 k-rows in SMEM

typedef unsigned long long u64;
typedef unsigned int u32;

// ---------------- device scratch --------------------------------------------
__device__ float g_pre[(size_t)TT * BB * G4];   // [t][b][512]
__device__ float g_hs0[(size_t)TT * BB * HH];   // [t][b][128]
__device__ float g_Mcomb[42 * 512];
__device__ float g_bias0[512];
__device__ float g_bias1[512];
__device__ float g_peproj[TT * 512];
__device__ float g_last[BB * HH];

// ---------------- f32x2 helpers ---------------------------------------------
#define FFMA2(d, a, b, c) \
    asm("fma.rn.f32x2 %0, %1, %2, %3;" : "=l"(d) : "l"(a), "l"(b), "l"(c))
#define PACK2(d, x) \
    asm("mov.b64 %0, {%1, %1};" : "=l"(d) : "r"(__float_as_uint(x)))
#define UNPK2(lo, hi, x) \
    asm("mov.b64 {%0, %1}, %2;" : "=r"(lo), "=r"(hi) : "l"(x))

__device__ __forceinline__ float sigf(float x) {
    return __fdividef(1.0f, 1.0f + __expf(-x));
}
__device__ __forceinline__ float tanhfast(float x) {
    float e = __expf(2.0f * x);
    return 1.0f - __fdividef(2.0f, e + 1.0f);
}

// ---------------- warp-MMA helpers -------------------------------------------
__device__ __forceinline__ u32 pack_h2(float a, float b) {
    __half2 h = __floats2half2_rn(a, b);   // a -> low, b -> high
    return *(u32*)&h;
}
#define MMA16816(C, A, B) \
    asm volatile("mma.sync.aligned.m16n8k16.row.col.f32.f16.f16.f32 " \
        "{%0,%1,%2,%3}, {%4,%5,%6,%7}, {%8,%9}, {%0,%1,%2,%3};" \
        : "+f"((C)[0]), "+f"((C)[1]), "+f"((C)[2]), "+f"((C)[3]) \
        : "r"((A)[0]), "r"((A)[1]), "r"((A)[2]), "r"((A)[3]), \
          "r"((B)[0]), "r"((B)[1]))

// ---------------- weight combine (unchanged, passing) ------------------------
__global__ __launch_bounds__(512) void k_comb(
                       const float* __restrict__ Wgcn, const float* __restrict__ bgcn,
                       const float* __restrict__ Wte,  const float* __restrict__ bte,
                       const float* __restrict__ Wih0, const float* __restrict__ bih0,
                       const float* __restrict__ bhh0, const float* __restrict__ bih1,
                       const float* __restrict__ bhh1) {
    int j = threadIdx.x;
    const float* wr = Wih0 + (size_t)j * KIN;
    for (int k = 0; k < 16; k++) {
        float s = 0.f;
        #pragma unroll 4
        for (int d = 0; d < 64; d++) s += Wgcn[k * 64 + d] * (wr[d] + wr[64 + d]);
        g_Mcomb[k * 512 + j] = 0.5f * s;
    }
    for (int k = 0; k < 26; k++) {
        float s = 0.f;
        #pragma unroll 4
        for (int d = 0; d < 64; d++) s += Wte[k * 64 + d] * wr[144 + d];
        g_Mcomb[(16 + k) * 512 + j] = s;
    }
    float b0 = bih0[j] + bhh0[j];
    #pragma unroll 4
    for (int d = 0; d < 64; d++) b0 += bgcn[d] * (wr[d] + wr[64 + d]) + bte[d] * wr[144 + d];
    g_bias0[j] = b0;
    g_bias1[j] = bih1[j] + bhh1[j];
}

// ---------------- positional encoding projection (unchanged) -----------------
__global__ __launch_bounds__(256) void k_pe(const float* __restrict__ Wih0) {
    int id = blockIdx.x * blockDim.x + threadIdx.x;
    if (id >= TT * 512) return;
    int t = id >> 9, j = id & 511;
    const float* wr = Wih0 + (size_t)j * KIN + 128;
    float acc = 0.f;
    #pragma unroll
    for (int i = 0; i < 8; i++) {
        float div = expf(-(float)(2 * i) * (9.210340371976184f / 16.0f));
        float ang = (float)t * div;
        acc += sinf(ang) * wr[2 * i] + cosf(ang) * wr[2 * i + 1];
    }
    g_peproj[id] = acc;
}

// ---------------- pre0 (unchanged, passing) ----------------------------------
__global__ __launch_bounds__(256, 1) void k_pre0(const float* __restrict__ xs,
                                                 const float* __restrict__ xt) {
    extern __shared__ float sm[];
    float* Msm = sm;               // [42][512]
    float* xT  = sm + 42 * 512;    // [42][8]
    int t = blockIdx.x, tid = threadIdx.x;
    int j0 = tid * 2;
    for (int i = tid; i < 42 * 512; i += 256) Msm[i] = g_Mcomb[i];
    u64 bj0, bj1;
    PACK2(bj0, g_bias0[j0]     + g_peproj[t * 512 + j0]);
    PACK2(bj1, g_bias0[j0 + 1] + g_peproj[t * 512 + j0 + 1]);
    __syncthreads();
    for (int bt = 0; bt < 64; bt++) {
        int bb = bt * 8;
        #pragma unroll
        for (int s = 0; s < 2; s++) {
            int i = tid + s * 256;
            if (i < 128) {
                int b = i >> 4, k = i & 15;
                const float* xp = xs + ((size_t)(bb + b) * TT + t) * 32;
                xT[k * 8 + b] = xp[k] + xp[k + 16];
            } else if (i < 336) {
                int idx = i - 128; int b = idx / 26, k = idx - b * 26;
                xT[(16 + k) * 8 + b] = xt[((size_t)(bb + b) * TT + t) * 26 + k];
            }
        }
        __syncthreads();
        u64 A[8];
        A[0] = bj0; A[1] = bj0; A[2] = bj0; A[3] = bj0;
        A[4] = bj1; A[5] = bj1; A[6] = bj1; A[7] = bj1;
        #pragma unroll 6
        for (int k = 0; k < 42; k++) {
            float2 w = *(const float2*)(Msm + k * 512 + j0);
            u64 wa, wb; PACK2(wa, w.x); PACK2(wb, w.y);
            ulonglong2 h0 = *(const ulonglong2*)(xT + k * 8);
            ulonglong2 h1 = *(const ulonglong2*)(xT + k * 8 + 4);
            FFMA2(A[0], wa, h0.x, A[0]); FFMA2(A[1], wa, h0.y, A[1]);
            FFMA2(A[2], wa, h1.x, A[2]); FFMA2(A[3], wa, h1.y, A[3]);
            FFMA2(A[4], wb, h0.x, A[4]); FFMA2(A[5], wb, h0.y, A[5]);
            FFMA2(A[6], wb, h1.x, A[6]); FFMA2(A[7], wb, h1.y, A[7]);
        }
        unsigned zj0[8], zj1[8];
        UNPK2(zj0[0], zj0[1], A[0]); UNPK2(zj0[2], zj0[3], A[1]);
        UNPK2(zj0[4], zj0[5], A[2]); UNPK2(zj0[6], zj0[7], A[3]);
        UNPK2(zj1[0], zj1[1], A[4]); UNPK2(zj1[2], zj1[3], A[5]);
        UNPK2(zj1[4], zj1[5], A[6]); UNPK2(zj1[6], zj1[7], A[7]);
        size_t po = ((size_t)t * BB + bb) * G4 + j0;
        #pragma unroll
        for (int b = 0; b < 8; b++)
            *(float2*)(g_pre + po + (size_t)b * G4) =
                make_float2(__uint_as_float(zj0[b]), __uint_as_float(zj1[b]));
        __syncthreads();
    }
}

// ---------------- pre1 (unchanged, passing) ----------------------------------
__global__ __launch_bounds__(256, 1) void k_pre1(const float* __restrict__ Wih1) {
    extern __shared__ float sm[];
    float* Wsm = sm;               // [KSM][512]
    float* hT8 = sm + KSM * 512;   // [128][8]
    int t = blockIdx.x, tid = threadIdx.x;
    int j0 = tid * 2;
    u64 w00[KREG], w11[KREG];
    #pragma unroll
    for (int k = 0; k < KREG; k++) {
        PACK2(w00[k], Wih1[(size_t)j0 * HH + k]);
        PACK2(w11[k], Wih1[(size_t)(j0 + 1) * HH + k]);
    }
    for (int i = tid; i < KSM * 512; i += 256) {
        int kk = i >> 9, jj = i & 511;
        Wsm[i] = Wih1[(size_t)jj * HH + KREG + kk];
    }
    u64 bj0, bj1;
    PACK2(bj0, g_bias1[j0]);
    PACK2(bj1, g_bias1[j0 + 1]);
    __syncthreads();
    for (int bt = 0; bt < 64; bt++) {
        int bb = bt * 8;
        #pragma unroll
        for (int s = 0; s < 4; s++) {
            int i = tid + s * 256;
            int b = i >> 7, k = i & 127;
            hT8[k * 8 + b] = g_hs0[((size_t)t * BB + bb + b) * HH + k];
        }
        __syncthreads();
        u64 A[8];
        A[0] = bj0; A[1] = bj0; A[2] = bj0; A[3] = bj0;
        A[4] = bj1; A[5] = bj1; A[6] = bj1; A[7] = bj1;
        #pragma unroll
        for (int k = 0; k < KREG; k++) {
            ulonglong2 h0 = *(const ulonglong2*)(hT8 + k * 8);
            ulonglong2 h1 = *(const ulonglong2*)(hT8 + k * 8 + 4);
            FFMA2(A[0], w00[k], h0.x, A[0]); FFMA2(A[1], w00[k], h0.y, A[1]);
            FFMA2(A[2], w00[k], h1.x, A[2]); FFMA2(A[3], w00[k], h1.y, A[3]);
            FFMA2(A[4], w11[k], h0.x, A[4]); FFMA2(A[5], w11[k], h0.y, A[5]);
            FFMA2(A[6], w11[k], h1.x, A[6]); FFMA2(A[7], w11[k], h1.y, A[7]);
        }
        #pragma unroll 4
        for (int k = KREG; k < 128; k++) {
            float2 w = *(const float2*)(Wsm + (k - KREG) * 512 + j0);
            u64 wa, wb; PACK2(wa, w.x); PACK2(wb, w.y);
            ulonglong2 h0 = *(const ulonglong2*)(hT8 + k * 8);
            ulonglong2 h1 = *(const ulonglong2*)(hT8 + k * 8 + 4);
            FFMA2(A[0], wa, h0.x, A[0]); FFMA2(A[1], wa, h0.y, A[1]);
            FFMA2(A[2], wa, h1.x, A[2]); FFMA2(A[3], wa, h1.y, A[3]);
            FFMA2(A[4], wb, h0.x, A[4]); FFMA2(A[5], wb, h0.y, A[5]);
            FFMA2(A[6], wb, h1.x, A[6]); FFMA2(A[7], wb, h1.y, A[7]);
        }
        unsigned zj0[8], zj1[8];
        UNPK2(zj0[0], zj0[1], A[0]); UNPK2(zj0[2], zj0[3], A[1]);
        UNPK2(zj0[4], zj0[5], A[2]); UNPK2(zj0[6], zj0[7], A[3]);
        UNPK2(zj1[0], zj1[1], A[4]); UNPK2(zj1[2], zj1[3], A[5]);
        UNPK2(zj1[4], zj1[5], A[6]); UNPK2(zj1[6], zj1[7], A[7]);
        size_t po = ((size_t)t * BB + bb) * G4 + j0;
        #pragma unroll
        for (int b = 0; b < 8; b++)
            *(float2*)(g_pre + po + (size_t)b * G4) =
                make_float2(__uint_as_float(zj0[b]), __uint_as_float(zj1[b]));
        __syncthreads();
    }
}

// ---------------- LSTM sweep via warp-level HMMA (m16n8k16) ------------------
// 128 CTAs x 4 batch rows, 256 threads (8 warps).
// Warp w owns m-tiles {w, w+8, w+16, w+24}: one 16-row tile PER GATE over the
// SAME u-range [w*16, w*16+16) -> i,f,g,o land in-thread, no z exchange.
// B tile hB[8][128+pad] fp16: rows 0-3 = h_hi[b], rows 4-7 = h_lo[b].
// One MMA pass computes hi products in accum cols 0-3 and lo products in cols
// 4-7; acc += shfl_xor(acc,2) combines. Accum initialized with pre-activations.
__global__ __launch_bounds__(256, 1)
void k_lstm(const float* __restrict__ Whh, int write_hs, int write_last) {
    __shared__ __half hB[8 * 136];     // [n][k], row stride 136 (bank-spread)
    int tid  = threadIdx.x;
    int w    = tid >> 5;
    int lane = tid & 31;
    int gid  = lane >> 2;              // 0..7
    int tig  = lane & 3;               // 0..3
    int bb   = blockIdx.x * 4;

    // A fragments: [gate][kt][4], fp16 from fp32 Whh
    u32 areg[4][8][4];
    #pragma unroll
    for (int gg = 0; gg < 4; gg++) {
        int r0 = (w + 8 * gg) * 16 + gid;
        const float* W0 = Whh + (size_t)r0 * HH;
        const float* W1 = Whh + (size_t)(r0 + 8) * HH;
        #pragma unroll
        for (int kt = 0; kt < 8; kt++) {
            int cc = kt * 16 + tig * 2;
            areg[gg][kt][0] = pack_h2(W0[cc], W0[cc + 1]);
            areg[gg][kt][1] = pack_h2(W1[cc], W1[cc + 1]);
            areg[gg][kt][2] = pack_h2(W0[cc + 8], W0[cc + 9]);
            areg[gg][kt][3] = pack_h2(W1[cc + 8], W1[cc + 9]);
        }
    }
    for (int i = tid; i < 8 * 136; i += 256) hB[i] = __float2half(0.f);

    int u0 = w * 16 + gid, u1 = u0 + 8;
    int b0 = tig * 2, b1 = b0 + 1;     // real batch cols only when tig < 2
    bool act = (tig < 2);
    float cs0 = 0.f, cs1 = 0.f, cs2 = 0.f, cs3 = 0.f;
    float hv0 = 0.f, hv1 = 0.f, hv2 = 0.f, hv3 = 0.f;
    __syncthreads();

    for (int t = 0; t < TT; t++) {
        // accumulators seeded with pre-activations (folds the +pre for free)
        float acc[4][4];
        if (act) {
            const float* P0 = g_pre + ((size_t)t * BB + bb + b0) * G4;
            const float* P1 = g_pre + ((size_t)t * BB + bb + b1) * G4;
            #pragma unroll
            for (int gg = 0; gg < 4; gg++) {
                acc[gg][0] = P0[gg * 128 + u0];
                acc[gg][1] = P1[gg * 128 + u0];
                acc[gg][2] = P0[gg * 128 + u1];
                acc[gg][3] = P1[gg * 128 + u1];
            }
        } else {
            #pragma unroll
            for (int gg = 0; gg < 4; gg++) {
                acc[gg][0] = 0.f; acc[gg][1] = 0.f;
                acc[gg][2] = 0.f; acc[gg][3] = 0.f;
            }
        }

        // B fragments: b0 halves = hB[gid][kt*16+2*tig .. +1], b1 = +8
        u32 bfr[8][2];
        #pragma unroll
        for (int kt = 0; kt < 8; kt++) {
            const u32* bp = (const u32*)(hB + gid * 136 + kt * 16 + tig * 2);
            bfr[kt][0] = bp[0];
            bfr[kt][1] = bp[4];
        }
        __syncthreads();                 // all hB reads done before writes below

        #pragma unroll
        for (int gg = 0; gg < 4; gg++) {
            #pragma unroll
            for (int kt = 0; kt < 8; kt++)
                MMA16816(acc[gg], areg[gg][kt], bfr[kt]);
        }

        // combine hi (cols 0-3) + lo (cols 4-7): partner lane = lane ^ 2
        #pragma unroll
        for (int gg = 0; gg < 4; gg++) {
            #pragma unroll
            for (int i = 0; i < 4; i++)
                acc[gg][i] += __shfl_xor_sync(0xFFFFFFFFu, acc[gg][i], 2);
        }

        if (act) {
            // (u0,b0)
            cs0 = sigf(acc[1][0]) * cs0 + sigf(acc[0][0]) * tanhfast(acc[2][0]);
            hv0 = sigf(acc[3][0]) * tanhfast(cs0);
            // (u0,b1)
            cs1 = sigf(acc[1][1]) * cs1 + sigf(acc[0][1]) * tanhfast(acc[2][1]);
            hv1 = sigf(acc[3][1]) * tanhfast(cs1);
            // (u1,b0)
            cs2 = sigf(acc[1][2]) * cs2 + sigf(acc[0][2]) * tanhfast(acc[2][2]);
            hv2 = sigf(acc[3][2]) * tanhfast(cs2);
            // (u1,b1)
            cs3 = sigf(acc[1][3]) * cs3 + sigf(acc[0][3]) * tanhfast(acc[2][3]);
            hv3 = sigf(acc[3][3]) * tanhfast(cs3);

            __half h0h = __float2half_rn(hv0);
            __half h1h = __float2half_rn(hv1);
            __half h2h = __float2half_rn(hv2);
            __half h3h = __float2half_rn(hv3);
            hB[b0 * 136 + u0] = h0h;
            hB[b1 * 136 + u0] = h1h;
            hB[b0 * 136 + u1] = h2h;
            hB[b1 * 136 + u1] = h3h;
            hB[(b0 + 4) * 136 + u0] = __float2half_rn(hv0 - __half2float(h0h));
            hB[(b1 + 4) * 136 + u0] = __float2half_rn(hv1 - __half2float(h1h));
            hB[(b0 + 4) * 136 + u1] = __float2half_rn(hv2 - __half2float(h2h));
            hB[(b1 + 4) * 136 + u1] = __float2half_rn(hv3 - __half2float(h3h));
            if (write_hs) {
                g_hs0[((size_t)t * BB + bb + b0) * HH + u0] = hv0;
                g_hs0[((size_t)t * BB + bb + b1) * HH + u0] = hv1;
                g_hs0[((size_t)t * BB + bb + b0) * HH + u1] = hv2;
                g_hs0[((size_t)t * BB + bb + b1) * HH + u1] = hv3;
            }
        }
        __syncthreads();
    }
    if (write_last && act) {
        g_last[(bb + b0) * HH + u0] = hv0;
        g_last[(bb + b1) * HH + u0] = hv1;
        g_last[(bb + b0) * HH + u1] = hv2;
        g_last[(bb + b1) * HH + u1] = hv3;
    }
}

// ---------------- MLP head (unchanged) ---------------------------------------
__global__ __launch_bounds__(128) void k_head(
                       const float* __restrict__ W1, const float* __restrict__ b1,
                       const float* __restrict__ W2, const float* __restrict__ b2,
                       const float* __restrict__ W3, const float* __restrict__ b3,
                       float* __restrict__ out) {
    __shared__ float xin[128], y1[128], y2[64];
    int b = blockIdx.x, j = threadIdx.x;
    xin[j] = g_last[b * HH + j];
    __syncthreads();
    float s = b1[j];
    #pragma unroll 4
    for (int k = 0; k < 128; k++) s += xin[k] * W1[j * 128 + k];
    y1[j] = fmaxf(s, 0.f);
    __syncthreads();
    if (j < 64) {
        float s2 = b2[j];
        #pragma unroll 4
        for (int k = 0; k < 128; k++) s2 += y1[k] * W2[j * 128 + k];
        y2[j] = fmaxf(s2, 0.f);
    }
    __syncthreads();
    if (j < 26) {
        float s3 = b3[j];
        #pragma unroll 4
        for (int k = 0; k < 64; k++) s3 += y2[k] * W3[j * 64 + k];
        out[b * 26 + j] = s3;
    }
}

// ---------------- launch -----------------------------------------------------
extern "C" void kernel_launch(void* const* d_in, const int* in_sizes, int n_in,
                              void* d_out, int out_size) {
    const float* xs   = (const float*)d_in[0];
    const float* xt   = (const float*)d_in[1];
    const float* Wgcn = (const float*)d_in[2];
    const float* bgcn = (const float*)d_in[3];
    const float* Wte  = (const float*)d_in[4];
    const float* bte  = (const float*)d_in[5];
    const float* Wih0 = (const float*)d_in[6];
    const float* Whh0 = (const float*)d_in[7];
    const float* bih0 = (const float*)d_in[8];
    const float* bhh0 = (const float*)d_in[9];
    const float* Wih1 = (const float*)d_in[10];
    const float* Whh1 = (const float*)d_in[11];
    const float* bih1 = (const float*)d_in[12];
    const float* bhh1 = (const float*)d_in[13];
    const float* W1   = (const float*)d_in[14];
    const float* b1   = (const float*)d_in[15];
    const float* W2   = (const float*)d_in[16];
    const float* b2   = (const float*)d_in[17];
    const float* W3   = (const float*)d_in[18];
    const float* b3   = (const float*)d_in[19];

    const int SM_PRE0 = (42 * 512 + 42 * 8) * 4;                  //  87,360 B
    const int SM_PRE1 = (KSM * 512 + 128 * 8) * 4;                // 167,936 B
    cudaFuncSetAttribute(k_pre0, cudaFuncAttributeMaxDynamicSharedMemorySize, SM_PRE0);
    cudaFuncSetAttribute(k_pre1, cudaFuncAttributeMaxDynamicSharedMemorySize, SM_PRE1);

    k_comb<<<1, 512>>>(Wgcn, bgcn, Wte, bte, Wih0, bih0, bhh0, bih1, bhh1);
    k_pe<<<(TT * 512 + 255) / 256, 256>>>(Wih0);
    k_pre0<<<TT, 256, SM_PRE0>>>(xs, xt);
    k_lstm<<<BB / 4, 256>>>(Whh0, 1, 0);            // layer 0 -> hs0
    k_pre1<<<TT, 256, SM_PRE1>>>(Wih1);             // g_pre := pre1
    k_lstm<<<BB / 4, 256>>>(Whh1, 0, 1);            // layer 1 -> last
    k_head<<<BB, 128>>>(W1, b1, W2, b2, W3, b3, (float*)d_out);
}

// round 13
// speedup vs baseline: 1.8050x; 1.1724x over previous
#include <cuda_runtime.h>
#include <cuda_fp16.h>
#include <cstdint>
#include <cstddef>
#include <math.h>

#define TT   1000
#define BB   512
#define HH   128
#define G4   512
#define KIN  208
#define KREG 48               // pre1: k-rows in registers
#define KSM  (HH - KREG)      // pre1: 80 k-rows in SMEM

typedef unsigned long long u64;
typedef unsigned int u32;

// ---------------- device scratch --------------------------------------------
__device__ float g_pre[(size_t)TT * BB * G4];   // [t][b][512]
__device__ float g_hs0[(size_t)TT * BB * HH];   // [t][b][128]
__device__ float g_Mcomb[42 * 512];
__device__ float g_bias0[512];
__device__ float g_bias1[512];
__device__ float g_peproj[TT * 512];
__device__ float g_last[BB * HH];

// ---------------- f32x2 helpers ---------------------------------------------
#define FFMA2(d, a, b, c) \
    asm("fma.rn.f32x2 %0, %1, %2, %3;" : "=l"(d) : "l"(a), "l"(b), "l"(c))
#define PACK2(d, x) \
    asm("mov.b64 %0, {%1, %1};" : "=l"(d) : "r"(__float_as_uint(x)))
#define UNPK2(lo, hi, x) \
    asm("mov.b64 {%0, %1}, %2;" : "=r"(lo), "=r"(hi) : "l"(x))

__device__ __forceinline__ float sigf(float x) {
    return __fdividef(1.0f, 1.0f + __expf(-x));
}
__device__ __forceinline__ float tanhfast(float x) {
    float e = __expf(2.0f * x);
    return 1.0f - __fdividef(2.0f, e + 1.0f);
}
// HW tanh (MUFU.TANH) + sigmoid built on it: 1 MUFU each vs 2 for exp+rcp
__device__ __forceinline__ float tanha(float x) {
    float y;
    asm("tanh.approx.f32 %0, %1;" : "=f"(y) : "f"(x));
    return y;
}
__device__ __forceinline__ float siga(float x) {
    return fmaf(tanha(0.5f * x), 0.5f, 0.5f);
}

// ---------------- warp-MMA / cp.async helpers --------------------------------
__device__ __forceinline__ u32 pack_h2(float a, float b) {
    __half2 h = __floats2half2_rn(a, b);   // a -> low, b -> high
    return *(u32*)&h;
}
#define MMA16816(C, A, B) \
    asm volatile("mma.sync.aligned.m16n8k16.row.col.f32.f16.f16.f32 " \
        "{%0,%1,%2,%3}, {%4,%5,%6,%7}, {%8,%9}, {%0,%1,%2,%3};" \
        : "+f"((C)[0]), "+f"((C)[1]), "+f"((C)[2]), "+f"((C)[3]) \
        : "r"((A)[0]), "r"((A)[1]), "r"((A)[2]), "r"((A)[3]), \
          "r"((B)[0]), "r"((B)[1]))
__device__ __forceinline__ u32 smem_u32(const void* p) {
    u32 a;
    asm("{ .reg .u64 t; cvta.to.shared.u64 t, %1; cvt.u32.u64 %0, t; }" : "=r"(a) : "l"(p));
    return a;
}
#define CP_ASYNC16(saddr, gptr) \
    asm volatile("cp.async.cg.shared.global [%0], [%1], 16;" :: "r"(saddr), "l"(gptr))
#define CP_COMMIT() asm volatile("cp.async.commit_group;" ::: "memory")
#define CP_WAIT0()  asm volatile("cp.async.wait_group 0;" ::: "memory")

// ---------------- weight combine (unchanged, passing) ------------------------
__global__ __launch_bounds__(512) void k_comb(
                       const float* __restrict__ Wgcn, const float* __restrict__ bgcn,
                       const float* __restrict__ Wte,  const float* __restrict__ bte,
                       const float* __restrict__ Wih0, const float* __restrict__ bih0,
                       const float* __restrict__ bhh0, const float* __restrict__ bih1,
                       const float* __restrict__ bhh1) {
    int j = threadIdx.x;
    const float* wr = Wih0 + (size_t)j * KIN;
    for (int k = 0; k < 16; k++) {
        float s = 0.f;
        #pragma unroll 4
        for (int d = 0; d < 64; d++) s += Wgcn[k * 64 + d] * (wr[d] + wr[64 + d]);
        g_Mcomb[k * 512 + j] = 0.5f * s;
    }
    for (int k = 0; k < 26; k++) {
        float s = 0.f;
        #pragma unroll 4
        for (int d = 0; d < 64; d++) s += Wte[k * 64 + d] * wr[144 + d];
        g_Mcomb[(16 + k) * 512 + j] = s;
    }
    float b0 = bih0[j] + bhh0[j];
    #pragma unroll 4
    for (int d = 0; d < 64; d++) b0 += bgcn[d] * (wr[d] + wr[64 + d]) + bte[d] * wr[144 + d];
    g_bias0[j] = b0;
    g_bias1[j] = bih1[j] + bhh1[j];
}

// ---------------- positional encoding projection (unchanged) -----------------
__global__ __launch_bounds__(256) void k_pe(const float* __restrict__ Wih0) {
    int id = blockIdx.x * blockDim.x + threadIdx.x;
    if (id >= TT * 512) return;
    int t = id >> 9, j = id & 511;
    const float* wr = Wih0 + (size_t)j * KIN + 128;
    float acc = 0.f;
    #pragma unroll
    for (int i = 0; i < 8; i++) {
        float div = expf(-(float)(2 * i) * (9.210340371976184f / 16.0f));
        float ang = (float)t * div;
        acc += sinf(ang) * wr[2 * i] + cosf(ang) * wr[2 * i + 1];
    }
    g_peproj[id] = acc;
}

// ---------------- pre0 (unchanged, passing) ----------------------------------
__global__ __launch_bounds__(256, 1) void k_pre0(const float* __restrict__ xs,
                                                 const float* __restrict__ xt) {
    extern __shared__ float sm[];
    float* Msm = sm;               // [42][512]
    float* xT  = sm + 42 * 512;    // [42][8]
    int t = blockIdx.x, tid = threadIdx.x;
    int j0 = tid * 2;
    for (int i = tid; i < 42 * 512; i += 256) Msm[i] = g_Mcomb[i];
    u64 bj0, bj1;
    PACK2(bj0, g_bias0[j0]     + g_peproj[t * 512 + j0]);
    PACK2(bj1, g_bias0[j0 + 1] + g_peproj[t * 512 + j0 + 1]);
    __syncthreads();
    for (int bt = 0; bt < 64; bt++) {
        int bb = bt * 8;
        #pragma unroll
        for (int s = 0; s < 2; s++) {
            int i = tid + s * 256;
            if (i < 128) {
                int b = i >> 4, k = i & 15;
                const float* xp = xs + ((size_t)(bb + b) * TT + t) * 32;
                xT[k * 8 + b] = xp[k] + xp[k + 16];
            } else if (i < 336) {
                int idx = i - 128; int b = idx / 26, k = idx - b * 26;
                xT[(16 + k) * 8 + b] = xt[((size_t)(bb + b) * TT + t) * 26 + k];
            }
        }
        __syncthreads();
        u64 A[8];
        A[0] = bj0; A[1] = bj0; A[2] = bj0; A[3] = bj0;
        A[4] = bj1; A[5] = bj1; A[6] = bj1; A[7] = bj1;
        #pragma unroll 6
        for (int k = 0; k < 42; k++) {
            float2 w = *(const float2*)(Msm + k * 512 + j0);
            u64 wa, wb; PACK2(wa, w.x); PACK2(wb, w.y);
            ulonglong2 h0 = *(const ulonglong2*)(xT + k * 8);
            ulonglong2 h1 = *(const ulonglong2*)(xT + k * 8 + 4);
            FFMA2(A[0], wa, h0.x, A[0]); FFMA2(A[1], wa, h0.y, A[1]);
            FFMA2(A[2], wa, h1.x, A[2]); FFMA2(A[3], wa, h1.y, A[3]);
            FFMA2(A[4], wb, h0.x, A[4]); FFMA2(A[5], wb, h0.y, A[5]);
            FFMA2(A[6], wb, h1.x, A[6]); FFMA2(A[7], wb, h1.y, A[7]);
        }
        unsigned zj0[8], zj1[8];
        UNPK2(zj0[0], zj0[1], A[0]); UNPK2(zj0[2], zj0[3], A[1]);
        UNPK2(zj0[4], zj0[5], A[2]); UNPK2(zj0[6], zj0[7], A[3]);
        UNPK2(zj1[0], zj1[1], A[4]); UNPK2(zj1[2], zj1[3], A[5]);
        UNPK2(zj1[4], zj1[5], A[6]); UNPK2(zj1[6], zj1[7], A[7]);
        size_t po = ((size_t)t * BB + bb) * G4 + j0;
        #pragma unroll
        for (int b = 0; b < 8; b++)
            *(float2*)(g_pre + po + (size_t)b * G4) =
                make_float2(__uint_as_float(zj0[b]), __uint_as_float(zj1[b]));
        __syncthreads();
    }
}

// ---------------- pre1 (unchanged, passing) ----------------------------------
__global__ __launch_bounds__(256, 1) void k_pre1(const float* __restrict__ Wih1) {
    extern __shared__ float sm[];
    float* Wsm = sm;               // [KSM][512]
    float* hT8 = sm + KSM * 512;   // [128][8]
    int t = blockIdx.x, tid = threadIdx.x;
    int j0 = tid * 2;
    u64 w00[KREG], w11[KREG];
    #pragma unroll
    for (int k = 0; k < KREG; k++) {
        PACK2(w00[k], Wih1[(size_t)j0 * HH + k]);
        PACK2(w11[k], Wih1[(size_t)(j0 + 1) * HH + k]);
    }
    for (int i = tid; i < KSM * 512; i += 256) {
        int kk = i >> 9, jj = i & 511;
        Wsm[i] = Wih1[(size_t)jj * HH + KREG + kk];
    }
    u64 bj0, bj1;
    PACK2(bj0, g_bias1[j0]);
    PACK2(bj1, g_bias1[j0 + 1]);
    __syncthreads();
    for (int bt = 0; bt < 64; bt++) {
        int bb = bt * 8;
        #pragma unroll
        for (int s = 0; s < 4; s++) {
            int i = tid + s * 256;
            int b = i >> 7, k = i & 127;
            hT8[k * 8 + b] = g_hs0[((size_t)t * BB + bb + b) * HH + k];
        }
        __syncthreads();
        u64 A[8];
        A[0] = bj0; A[1] = bj0; A[2] = bj0; A[3] = bj0;
        A[4] = bj1; A[5] = bj1; A[6] = bj1; A[7] = bj1;
        #pragma unroll
        for (int k = 0; k < KREG; k++) {
            ulonglong2 h0 = *(const ulonglong2*)(hT8 + k * 8);
            ulonglong2 h1 = *(const ulonglong2*)(hT8 + k * 8 + 4);
            FFMA2(A[0], w00[k], h0.x, A[0]); FFMA2(A[1], w00[k], h0.y, A[1]);
            FFMA2(A[2], w00[k], h1.x, A[2]); FFMA2(A[3], w00[k], h1.y, A[3]);
            FFMA2(A[4], w11[k], h0.x, A[4]); FFMA2(A[5], w11[k], h0.y, A[5]);
            FFMA2(A[6], w11[k], h1.x, A[6]); FFMA2(A[7], w11[k], h1.y, A[7]);
        }
        #pragma unroll 4
        for (int k = KREG; k < 128; k++) {
            float2 w = *(const float2*)(Wsm + (k - KREG) * 512 + j0);
            u64 wa, wb; PACK2(wa, w.x); PACK2(wb, w.y);
            ulonglong2 h0 = *(const ulonglong2*)(hT8 + k * 8);
            ulonglong2 h1 = *(const ulonglong2*)(hT8 + k * 8 + 4);
            FFMA2(A[0], wa, h0.x, A[0]); FFMA2(A[1], wa, h0.y, A[1]);
            FFMA2(A[2], wa, h1.x, A[2]); FFMA2(A[3], wa, h1.y, A[3]);
            FFMA2(A[4], wb, h0.x, A[4]); FFMA2(A[5], wb, h0.y, A[5]);
            FFMA2(A[6], wb, h1.x, A[6]); FFMA2(A[7], wb, h1.y, A[7]);
        }
        unsigned zj0[8], zj1[8];
        UNPK2(zj0[0], zj0[1], A[0]); UNPK2(zj0[2], zj0[3], A[1]);
        UNPK2(zj0[4], zj0[5], A[2]); UNPK2(zj0[6], zj0[7], A[3]);
        UNPK2(zj1[0], zj1[1], A[4]); UNPK2(zj1[2], zj1[3], A[5]);
        UNPK2(zj1[4], zj1[5], A[6]); UNPK2(zj1[6], zj1[7], A[7]);
        size_t po = ((size_t)t * BB + bb) * G4 + j0;
        #pragma unroll
        for (int b = 0; b < 8; b++)
            *(float2*)(g_pre + po + (size_t)b * G4) =
                make_float2(__uint_as_float(zj0[b]), __uint_as_float(zj1[b]));
        __syncthreads();
    }
}

// ---------------- LSTM sweep: warp HMMA + cp.async prefetch + MUFU.TANH ------
// 128 CTAs x 4 batch rows, 256 threads (8 warps). Warp w owns m-tiles
// {w, w+8, w+16, w+24} = gates i,f,g,o over u in [w*16, w*16+16) -> in-thread
// gate phase. hB[8][136] fp16: rows 0-3 h_hi, 4-7 h_lo; hi+lo combined via
// shfl_xor(2). g_pre seeds stream through a cp.async double buffer so DRAM
// latency overlaps the previous step's MMAs/gates.
__global__ __launch_bounds__(256, 1)
void k_lstm(const float* __restrict__ Whh, int write_hs, int write_last) {
    __shared__ __half hB[8 * 136];
    __shared__ __align__(16) float sbuf[2][2048];   // [p][b(4)][512]
    int tid  = threadIdx.x;
    int w    = tid >> 5;
    int lane = tid & 31;
    int gid  = lane >> 2;              // 0..7
    int tig  = lane & 3;               // 0..3
    int bb   = blockIdx.x * 4;

    // A fragments: [gate][kt][4], fp16 from fp32 Whh
    u32 areg[4][8][4];
    #pragma unroll
    for (int gg = 0; gg < 4; gg++) {
        int r0 = (w + 8 * gg) * 16 + gid;
        const float* W0 = Whh + (size_t)r0 * HH;
        const float* W1 = Whh + (size_t)(r0 + 8) * HH;
        #pragma unroll
        for (int kt = 0; kt < 8; kt++) {
            int cc = kt * 16 + tig * 2;
            areg[gg][kt][0] = pack_h2(W0[cc], W0[cc + 1]);
            areg[gg][kt][1] = pack_h2(W1[cc], W1[cc + 1]);
            areg[gg][kt][2] = pack_h2(W0[cc + 8], W0[cc + 9]);
            areg[gg][kt][3] = pack_h2(W1[cc + 8], W1[cc + 9]);
        }
    }
    for (int i = tid; i < 8 * 136; i += 256) hB[i] = __float2half(0.f);

    u32 sb0 = smem_u32(&sbuf[0][0]);
    u32 sb1 = smem_u32(&sbuf[1][0]);
    // preload step 0 into buffer 0
    {
        const float* gsrc = g_pre + (size_t)bb * G4;
        CP_ASYNC16(sb0 + (u32)tid * 16u, gsrc + tid * 4);
        CP_ASYNC16(sb0 + (u32)(tid + 256) * 16u, gsrc + (tid + 256) * 4);
        CP_COMMIT();
        CP_WAIT0();
    }

    int u0 = w * 16 + gid, u1 = u0 + 8;
    int b0 = tig * 2, b1 = b0 + 1;     // real batch cols only when tig < 2
    bool act = (tig < 2);
    float cs0 = 0.f, cs1 = 0.f, cs2 = 0.f, cs3 = 0.f;
    float hv0 = 0.f, hv1 = 0.f, hv2 = 0.f, hv3 = 0.f;
    __syncthreads();

    for (int t = 0; t < TT; t++) {
        int p = t & 1;
        const float* sp = sbuf[p];

        // seed accumulators with pre-activations from SMEM (LDS, not DRAM)
        float acc[4][4];
        if (act) {
            #pragma unroll
            for (int gg = 0; gg < 4; gg++) {
                acc[gg][0] = sp[b0 * 512 + gg * 128 + u0];
                acc[gg][1] = sp[b1 * 512 + gg * 128 + u0];
                acc[gg][2] = sp[b0 * 512 + gg * 128 + u1];
                acc[gg][3] = sp[b1 * 512 + gg * 128 + u1];
            }
        } else {
            #pragma unroll
            for (int gg = 0; gg < 4; gg++) {
                acc[gg][0] = 0.f; acc[gg][1] = 0.f;
                acc[gg][2] = 0.f; acc[gg][3] = 0.f;
            }
        }

        // prefetch step t+1 into the other buffer (overlaps MMAs + gates)
        if (t + 1 < TT) {
            u32 dst = (p ? sb0 : sb1);
            const float* gsrc = g_pre + ((size_t)(t + 1) * BB + bb) * G4;
            CP_ASYNC16(dst + (u32)tid * 16u, gsrc + tid * 4);
            CP_ASYNC16(dst + (u32)(tid + 256) * 16u, gsrc + (tid + 256) * 4);
        }
        CP_COMMIT();

        // B fragments: b0 halves = hB[gid][kt*16+2*tig .. +1], b1 = +8
        u32 bfr[8][2];
        #pragma unroll
        for (int kt = 0; kt < 8; kt++) {
            const u32* bp = (const u32*)(hB + gid * 136 + kt * 16 + tig * 2);
            bfr[kt][0] = bp[0];
            bfr[kt][1] = bp[4];
        }
        __syncthreads();                 // all hB reads done before writes below

        #pragma unroll
        for (int gg = 0; gg < 4; gg++) {
            #pragma unroll
            for (int kt = 0; kt < 8; kt++)
                MMA16816(acc[gg], areg[gg][kt], bfr[kt]);
        }

        // combine hi (cols 0-3) + lo (cols 4-7): partner lane = lane ^ 2
        #pragma unroll
        for (int gg = 0; gg < 4; gg++) {
            #pragma unroll
            for (int i = 0; i < 4; i++)
                acc[gg][i] += __shfl_xor_sync(0xFFFFFFFFu, acc[gg][i], 2);
        }

        if (act) {
            cs0 = siga(acc[1][0]) * cs0 + siga(acc[0][0]) * tanha(acc[2][0]);
            hv0 = siga(acc[3][0]) * tanha(cs0);
            cs1 = siga(acc[1][1]) * cs1 + siga(acc[0][1]) * tanha(acc[2][1]);
            hv1 = siga(acc[3][1]) * tanha(cs1);
            cs2 = siga(acc[1][2]) * cs2 + siga(acc[0][2]) * tanha(acc[2][2]);
            hv2 = siga(acc[3][2]) * tanha(cs2);
            cs3 = siga(acc[1][3]) * cs3 + siga(acc[0][3]) * tanha(acc[2][3]);
            hv3 = siga(acc[3][3]) * tanha(cs3);

            __half h0h = __float2half_rn(hv0);
            __half h1h = __float2half_rn(hv1);
            __half h2h = __float2half_rn(hv2);
            __half h3h = __float2half_rn(hv3);
            hB[b0 * 136 + u0] = h0h;
            hB[b1 * 136 + u0] = h1h;
            hB[b0 * 136 + u1] = h2h;
            hB[b1 * 136 + u1] = h3h;
            hB[(b0 + 4) * 136 + u0] = __float2half_rn(hv0 - __half2float(h0h));
            hB[(b1 + 4) * 136 + u0] = __float2half_rn(hv1 - __half2float(h1h));
            hB[(b0 + 4) * 136 + u1] = __float2half_rn(hv2 - __half2float(h2h));
            hB[(b1 + 4) * 136 + u1] = __float2half_rn(hv3 - __half2float(h3h));
            if (write_hs) {
                g_hs0[((size_t)t * BB + bb + b0) * HH + u0] = hv0;
                g_hs0[((size_t)t * BB + bb + b1) * HH + u0] = hv1;
                g_hs0[((size_t)t * BB + bb + b0) * HH + u1] = hv2;
                g_hs0[((size_t)t * BB + bb + b1) * HH + u1] = hv3;
            }
        }
        CP_WAIT0();                      // t+1 buffer landed (own copies)
        __syncthreads();                 // visibility of hB + sbuf to all
    }
    if (write_last && act) {
        g_last[(bb + b0) * HH + u0] = hv0;
        g_last[(bb + b1) * HH + u0] = hv1;
        g_last[(bb + b0) * HH + u1] = hv2;
        g_last[(bb + b1) * HH + u1] = hv3;
    }
}

// ---------------- MLP head (unchanged) ---------------------------------------
__global__ __launch_bounds__(128) void k_head(
                       const float* __restrict__ W1, const float* __restrict__ b1,
                       const float* __restrict__ W2, const float* __restrict__ b2,
                       const float* __restrict__ W3, const float* __restrict__ b3,
                       float* __restrict__ out) {
    __shared__ float xin[128], y1[128], y2[64];
    int b = blockIdx.x, j = threadIdx.x;
    xin[j] = g_last[b * HH + j];
    __syncthreads();
    float s = b1[j];
    #pragma unroll 4
    for (int k = 0; k < 128; k++) s += xin[k] * W1[j * 128 + k];
    y1[j] = fmaxf(s, 0.f);
    __syncthreads();
    if (j < 64) {
        float s2 = b2[j];
        #pragma unroll 4
        for (int k = 0; k < 128; k++) s2 += y1[k] * W2[j * 128 + k];
        y2[j] = fmaxf(s2, 0.f);
    }
    __syncthreads();
    if (j < 26) {
        float s3 = b3[j];
        #pragma unroll 4
        for (int k = 0; k < 64; k++) s3 += y2[k] * W3[j * 64 + k];
        out[b * 26 + j] = s3;
    }
}

// ---------------- launch -----------------------------------------------------
extern "C" void kernel_launch(void* const* d_in, const int* in_sizes, int n_in,
                              void* d_out, int out_size) {
    const float* xs   = (const float*)d_in[0];
    const float* xt   = (const float*)d_in[1];
    const float* Wgcn = (const float*)d_in[2];
    const float* bgcn = (const float*)d_in[3];
    const float* Wte  = (const float*)d_in[4];
    const float* bte  = (const float*)d_in[5];
    const float* Wih0 = (const float*)d_in[6];
    const float* Whh0 = (const float*)d_in[7];
    const float* bih0 = (const float*)d_in[8];
    const float* bhh0 = (const float*)d_in[9];
    const float* Wih1 = (const float*)d_in[10];
    const float* Whh1 = (const float*)d_in[11];
    const float* bih1 = (const float*)d_in[12];
    const float* bhh1 = (const float*)d_in[13];
    const float* W1   = (const float*)d_in[14];
    const float* b1   = (const float*)d_in[15];
    const float* W2   = (const float*)d_in[16];
    const float* b2   = (const float*)d_in[17];
    const float* W3   = (const float*)d_in[18];
    const float* b3   = (const float*)d_in[19];

    const int SM_PRE0 = (42 * 512 + 42 * 8) * 4;                  //  87,360 B
    const int SM_PRE1 = (KSM * 512 + 128 * 8) * 4;                // 167,936 B
    cudaFuncSetAttribute(k_pre0, cudaFuncAttributeMaxDynamicSharedMemorySize, SM_PRE0);
    cudaFuncSetAttribute(k_pre1, cudaFuncAttributeMaxDynamicSharedMemorySize, SM_PRE1);

    k_comb<<<1, 512>>>(Wgcn, bgcn, Wte, bte, Wih0, bih0, bhh0, bih1, bhh1);
    k_pe<<<(TT * 512 + 255) / 256, 256>>>(Wih0);
    k_pre0<<<TT, 256, SM_PRE0>>>(xs, xt);
    k_lstm<<<BB / 4, 256>>>(Whh0, 1, 0);            // layer 0 -> hs0
    k_pre1<<<TT, 256, SM_PRE1>>>(Wih1);             // g_pre := pre1
    k_lstm<<<BB / 4, 256>>>(Whh1, 0, 1);            // layer 1 -> last
    k_head<<<BB, 128>>>(W1, b1, W2, b2, W3, b3, (float*)d_out);
}

// round 15
// speedup vs baseline: 2.1179x; 1.1734x over previous
#include <cuda_runtime.h>
#include <cuda_fp16.h>
#include <cstdint>
#include <cstddef>
#include <math.h>

#define TT   1000
#define BB   512
#define HH   128
#define G4   512
#define KIN  208

typedef unsigned long long u64;
typedef unsigned int u32;

// ---------------- device scratch --------------------------------------------
// g_pre layout: [t][j(512)][b(512)]  (transposed vs earlier rounds)
__device__ float g_pre[(size_t)TT * BB * G4];
__device__ float g_hs0[(size_t)TT * BB * HH];   // [t][b][128]
__device__ float g_Mcomb[42 * 512];
__device__ float g_bias0[512];
__device__ float g_bias1[512];
__device__ float g_peproj[TT * 512];
__device__ float g_last[BB * HH];

// ---------------- f32x2 helpers ---------------------------------------------
#define FFMA2(d, a, b, c) \
    asm("fma.rn.f32x2 %0, %1, %2, %3;" : "=l"(d) : "l"(a), "l"(b), "l"(c))
#define PACK2(d, x) \
    asm("mov.b64 %0, {%1, %1};" : "=l"(d) : "r"(__float_as_uint(x)))
#define UNPK2(lo, hi, x) \
    asm("mov.b64 {%0, %1}, %2;" : "=r"(lo), "=r"(hi) : "l"(x))

__device__ __forceinline__ float tanha(float x) {
    float y;
    asm("tanh.approx.f32 %0, %1;" : "=f"(y) : "f"(x));
    return y;
}
__device__ __forceinline__ float siga(float x) {
    return fmaf(tanha(0.5f * x), 0.5f, 0.5f);
}

// ---------------- warp-MMA / cp.async helpers --------------------------------
__device__ __forceinline__ u32 pack_h2(float a, float b) {
    __half2 h = __floats2half2_rn(a, b);
    return *(u32*)&h;
}
#define MMA16816(C, A, B) \
    asm volatile("mma.sync.aligned.m16n8k16.row.col.f32.f16.f16.f32 " \
        "{%0,%1,%2,%3}, {%4,%5,%6,%7}, {%8,%9}, {%0,%1,%2,%3};" \
        : "+f"((C)[0]), "+f"((C)[1]), "+f"((C)[2]), "+f"((C)[3]) \
        : "r"((A)[0]), "r"((A)[1]), "r"((A)[2]), "r"((A)[3]), \
          "r"((B)[0]), "r"((B)[1]))
__device__ __forceinline__ u32 smem_u32(const void* p) {
    u32 a;
    asm("{ .reg .u64 t; cvta.to.shared.u64 t, %1; cvt.u32.u64 %0, t; }" : "=r"(a) : "l"(p));
    return a;
}
#define CP_ASYNC16(saddr, gptr) \
    asm volatile("cp.async.cg.shared.global [%0], [%1], 16;" :: "r"(saddr), "l"(gptr))
#define CP_COMMIT() asm volatile("cp.async.commit_group;" ::: "memory")
#define CP_WAIT0()  asm volatile("cp.async.wait_group 0;" ::: "memory")
#define CP_WAIT1()  asm volatile("cp.async.wait_group 1;" ::: "memory")

// ---------------- weight combine (unchanged, passing) ------------------------
__global__ __launch_bounds__(512) void k_comb(
                       const float* __restrict__ Wgcn, const float* __restrict__ bgcn,
                       const float* __restrict__ Wte,  const float* __restrict__ bte,
                       const float* __restrict__ Wih0, const float* __restrict__ bih0,
                       const float* __restrict__ bhh0, const float* __restrict__ bih1,
                       const float* __restrict__ bhh1) {
    int j = threadIdx.x;
    const float* wr = Wih0 + (size_t)j * KIN;
    for (int k = 0; k < 16; k++) {
        float s = 0.f;
        #pragma unroll 4
        for (int d = 0; d < 64; d++) s += Wgcn[k * 64 + d] * (wr[d] + wr[64 + d]);
        g_Mcomb[k * 512 + j] = 0.5f * s;
    }
    for (int k = 0; k < 26; k++) {
        float s = 0.f;
        #pragma unroll 4
        for (int d = 0; d < 64; d++) s += Wte[k * 64 + d] * wr[144 + d];
        g_Mcomb[(16 + k) * 512 + j] = s;
    }
    float b0 = bih0[j] + bhh0[j];
    #pragma unroll 4
    for (int d = 0; d < 64; d++) b0 += bgcn[d] * (wr[d] + wr[64 + d]) + bte[d] * wr[144 + d];
    g_bias0[j] = b0;
    g_bias1[j] = bih1[j] + bhh1[j];
}

// ---------------- positional encoding projection (unchanged) -----------------
__global__ __launch_bounds__(256) void k_pe(const float* __restrict__ Wih0) {
    int id = blockIdx.x * blockDim.x + threadIdx.x;
    if (id >= TT * 512) return;
    int t = id >> 9, j = id & 511;
    const float* wr = Wih0 + (size_t)j * KIN + 128;
    float acc = 0.f;
    #pragma unroll
    for (int i = 0; i < 8; i++) {
        float div = expf(-(float)(2 * i) * (9.210340371976184f / 16.0f));
        float ang = (float)t * div;
        acc += sinf(ang) * wr[2 * i] + cosf(ang) * wr[2 * i + 1];
    }
    g_peproj[id] = acc;
}

// ---------------- pre0: g_pre[t][j][b] = x42 @ M + pe + bias0 (f32x2) --------
__global__ __launch_bounds__(256, 1) void k_pre0(const float* __restrict__ xs,
                                                 const float* __restrict__ xt) {
    extern __shared__ float sm[];
    float* Msm = sm;               // [42][512]
    float* xT  = sm + 42 * 512;    // [42][8]
    int t = blockIdx.x, tid = threadIdx.x;
    int j0 = tid * 2;
    for (int i = tid; i < 42 * 512; i += 256) Msm[i] = g_Mcomb[i];
    u64 bj0, bj1;
    PACK2(bj0, g_bias0[j0]     + g_peproj[t * 512 + j0]);
    PACK2(bj1, g_bias0[j0 + 1] + g_peproj[t * 512 + j0 + 1]);
    __syncthreads();
    for (int bt = 0; bt < 64; bt++) {
        int bb = bt * 8;
        #pragma unroll
        for (int s = 0; s < 2; s++) {
            int i = tid + s * 256;
            if (i < 128) {
                int b = i >> 4, k = i & 15;
                const float* xp = xs + ((size_t)(bb + b) * TT + t) * 32;
                xT[k * 8 + b] = xp[k] + xp[k + 16];
            } else if (i < 336) {
                int idx = i - 128; int b = idx / 26, k = idx - b * 26;
                xT[(16 + k) * 8 + b] = xt[((size_t)(bb + b) * TT + t) * 26 + k];
            }
        }
        __syncthreads();
        u64 A[8];
        A[0] = bj0; A[1] = bj0; A[2] = bj0; A[3] = bj0;
        A[4] = bj1; A[5] = bj1; A[6] = bj1; A[7] = bj1;
        #pragma unroll 6
        for (int k = 0; k < 42; k++) {
            float2 w = *(const float2*)(Msm + k * 512 + j0);
            u64 wa, wb; PACK2(wa, w.x); PACK2(wb, w.y);
            ulonglong2 h0 = *(const ulonglong2*)(xT + k * 8);
            ulonglong2 h1 = *(const ulonglong2*)(xT + k * 8 + 4);
            FFMA2(A[0], wa, h0.x, A[0]); FFMA2(A[1], wa, h0.y, A[1]);
            FFMA2(A[2], wa, h1.x, A[2]); FFMA2(A[3], wa, h1.y, A[3]);
            FFMA2(A[4], wb, h0.x, A[4]); FFMA2(A[5], wb, h0.y, A[5]);
            FFMA2(A[6], wb, h1.x, A[6]); FFMA2(A[7], wb, h1.y, A[7]);
        }
        unsigned zj0[8], zj1[8];
        UNPK2(zj0[0], zj0[1], A[0]); UNPK2(zj0[2], zj0[3], A[1]);
        UNPK2(zj0[4], zj0[5], A[2]); UNPK2(zj0[6], zj0[7], A[3]);
        UNPK2(zj1[0], zj1[1], A[4]); UNPK2(zj1[2], zj1[3], A[5]);
        UNPK2(zj1[4], zj1[5], A[6]); UNPK2(zj1[6], zj1[7], A[7]);
        // transposed store: [t][j][bb..bb+8)
        size_t p0 = ((size_t)t * G4 + j0) * 512 + bb;
        size_t p1 = ((size_t)t * G4 + j0 + 1) * 512 + bb;
        *(float4*)(g_pre + p0) = make_float4(
            __uint_as_float(zj0[0]), __uint_as_float(zj0[1]),
            __uint_as_float(zj0[2]), __uint_as_float(zj0[3]));
        *(float4*)(g_pre + p0 + 4) = make_float4(
            __uint_as_float(zj0[4]), __uint_as_float(zj0[5]),
            __uint_as_float(zj0[6]), __uint_as_float(zj0[7]));
        *(float4*)(g_pre + p1) = make_float4(
            __uint_as_float(zj1[0]), __uint_as_float(zj1[1]),
            __uint_as_float(zj1[2]), __uint_as_float(zj1[3]));
        *(float4*)(g_pre + p1 + 4) = make_float4(
            __uint_as_float(zj1[4]), __uint_as_float(zj1[5]),
            __uint_as_float(zj1[6]), __uint_as_float(zj1[7]));
        __syncthreads();
    }
}

// ---------------- pre1 via warp HMMA -----------------------------------------
// One CTA per t. out[j=512][b=512] = Wih1[j][k] @ hs0[t][b][k]^T + bias1.
// Same fragment scheme as k_lstm: W fp16 in regs (warp w: j-tiles {w,w+8,w+16,
// w+24}), h hi/lo-split fp16 planes (n cols 0-3 hi / 4-7 lo, shfl_xor(2)).
// hs0 streams in 64-batch chunks: cp.async fp32 double buffer -> cooperative
// convert -> fp16 planes.
#define P1_STRIDE 144
__global__ __launch_bounds__(256, 1) void k_pre1(const float* __restrict__ Wih1) {
    extern __shared__ char smp[];
    float*  stage  = (float*)smp;                       // [2][64*128] = 64 KB
    __half* planeH = (__half*)(smp + 65536);            // [64][144]
    __half* planeL = planeH + 64 * P1_STRIDE;           // [64][144]
    u32 stage_s = smem_u32(stage);

    int t = blockIdx.x, tid = threadIdx.x;
    int w = tid >> 5, lane = tid & 31;
    int gid = lane >> 2, tig = lane & 3;
    bool act = (tig < 2);

    // A fragments: Wih1 fp16 (identical layout to k_lstm's Whh frags)
    u32 areg[4][8][4];
    float bias[8];
    #pragma unroll
    for (int gg = 0; gg < 4; gg++) {
        int r0 = (w + 8 * gg) * 16 + gid;
        const float* W0 = Wih1 + (size_t)r0 * HH;
        const float* W1 = Wih1 + (size_t)(r0 + 8) * HH;
        #pragma unroll
        for (int kt = 0; kt < 8; kt++) {
            int cc = kt * 16 + tig * 2;
            areg[gg][kt][0] = pack_h2(W0[cc], W0[cc + 1]);
            areg[gg][kt][1] = pack_h2(W1[cc], W1[cc + 1]);
            areg[gg][kt][2] = pack_h2(W0[cc + 8], W0[cc + 9]);
            areg[gg][kt][3] = pack_h2(W1[cc + 8], W1[cc + 9]);
        }
        bias[gg * 2]     = g_bias1[r0];
        bias[gg * 2 + 1] = g_bias1[r0 + 8];
    }

    // preload chunk 0
    {
        const float* src = g_hs0 + (size_t)t * BB * HH;
        #pragma unroll
        for (int i = 0; i < 8; i++)
            CP_ASYNC16(stage_s + (u32)(tid + i * 256) * 16u, src + (tid + i * 256) * 4);
        CP_COMMIT();
    }

    for (int c = 0; c < 8; c++) {
        if (c < 7) {
            const float* src = g_hs0 + ((size_t)t * BB + (c + 1) * 64) * HH;
            u32 dst = stage_s + (u32)((c + 1) & 1) * 32768u;
            #pragma unroll
            for (int i = 0; i < 8; i++)
                CP_ASYNC16(dst + (u32)(tid + i * 256) * 16u, src + (tid + i * 256) * 4);
            CP_COMMIT();
            CP_WAIT1();
        } else {
            CP_WAIT0();
        }
        __syncthreads();
        // convert chunk c (fp32) -> hi/lo fp16 planes
        const float* st = stage + (c & 1) * 8192;
        #pragma unroll
        for (int i = 0; i < 8; i++) {
            int idx4 = tid + i * 256;              // 0..2047 float4s
            float4 v = *(const float4*)(st + (size_t)idx4 * 4);
            int row = idx4 >> 5;                   // 64 rows
            int col = (idx4 & 31) * 4;
            __half h0 = __float2half_rn(v.x), h1 = __float2half_rn(v.y);
            __half h2 = __float2half_rn(v.z), h3 = __float2half_rn(v.w);
            __half l0 = __float2half_rn(v.x - __half2float(h0));
            __half l1 = __float2half_rn(v.y - __half2float(h1));
            __half l2 = __float2half_rn(v.z - __half2float(h2));
            __half l3 = __float2half_rn(v.w - __half2float(h3));
            __half2* ph = (__half2*)(planeH + row * P1_STRIDE + col);
            __half2* pl = (__half2*)(planeL + row * P1_STRIDE + col);
            ph[0] = __halves2half2(h0, h1); ph[1] = __halves2half2(h2, h3);
            pl[0] = __halves2half2(l0, l1); pl[1] = __halves2half2(l2, l3);
        }
        __syncthreads();

        const __half* pb = ((gid < 4) ? planeH : planeL) + (gid & 3) * P1_STRIDE;
        for (int grp = 0; grp < 16; grp++) {
            float acc[4][4];
            #pragma unroll
            for (int gg = 0; gg < 4; gg++) {
                float b0v = act ? bias[gg * 2] : 0.f;
                float b1v = act ? bias[gg * 2 + 1] : 0.f;
                acc[gg][0] = b0v; acc[gg][1] = b0v;
                acc[gg][2] = b1v; acc[gg][3] = b1v;
            }
            const __half* pr = pb + grp * 4 * P1_STRIDE;
            u32 bfr[8][2];
            #pragma unroll
            for (int kt = 0; kt < 8; kt++) {
                bfr[kt][0] = *(const u32*)(pr + kt * 16 + tig * 2);
                bfr[kt][1] = *(const u32*)(pr + kt * 16 + tig * 2 + 8);
            }
            #pragma unroll
            for (int gg = 0; gg < 4; gg++) {
                #pragma unroll
                for (int kt = 0; kt < 8; kt++)
                    MMA16816(acc[gg], areg[gg][kt], bfr[kt]);
            }
            #pragma unroll
            for (int gg = 0; gg < 4; gg++) {
                #pragma unroll
                for (int i = 0; i < 4; i++)
                    acc[gg][i] += __shfl_xor_sync(0xFFFFFFFFu, acc[gg][i], 2);
            }
            if (act) {
                int b0 = c * 64 + grp * 4 + tig * 2;
                #pragma unroll
                for (int gg = 0; gg < 4; gg++) {
                    int j0 = (w + 8 * gg) * 16 + gid;
                    *(float2*)(g_pre + ((size_t)t * G4 + j0) * 512 + b0) =
                        make_float2(acc[gg][0], acc[gg][1]);
                    *(float2*)(g_pre + ((size_t)t * G4 + j0 + 8) * 512 + b0) =
                        make_float2(acc[gg][2], acc[gg][3]);
                }
            }
        }
        __syncthreads();
    }
}

// ---------------- LSTM sweep: warp HMMA + cp.async prefetch + MUFU.TANH ------
// (unchanged logic from R13; only g_pre indexing updated to [t][j][b] layout)
__global__ __launch_bounds__(256, 1)
void k_lstm(const float* __restrict__ Whh, int write_hs, int write_last) {
    __shared__ __half hB[8 * 136];
    __shared__ __align__(16) float sbuf[2][2048];   // [p][j(512)][4b]
    int tid  = threadIdx.x;
    int w    = tid >> 5;
    int lane = tid & 31;
    int gid  = lane >> 2;
    int tig  = lane & 3;
    int bb   = blockIdx.x * 4;

    u32 areg[4][8][4];
    #pragma unroll
    for (int gg = 0; gg < 4; gg++) {
        int r0 = (w + 8 * gg) * 16 + gid;
        const float* W0 = Whh + (size_t)r0 * HH;
        const float* W1 = Whh + (size_t)(r0 + 8) * HH;
        #pragma unroll
        for (int kt = 0; kt < 8; kt++) {
            int cc = kt * 16 + tig * 2;
            areg[gg][kt][0] = pack_h2(W0[cc], W0[cc + 1]);
            areg[gg][kt][1] = pack_h2(W1[cc], W1[cc + 1]);
            areg[gg][kt][2] = pack_h2(W0[cc + 8], W0[cc + 9]);
            areg[gg][kt][3] = pack_h2(W1[cc + 8], W1[cc + 9]);
        }
    }
    for (int i = tid; i < 8 * 136; i += 256) hB[i] = __float2half(0.f);

    u32 sb0 = smem_u32(&sbuf[0][0]);
    u32 sb1 = smem_u32(&sbuf[1][0]);
    // preload step 0 ([t=0][j][bb..bb+4) -> 16B granule per j)
    CP_ASYNC16(sb0 + (u32)tid * 16u, g_pre + (size_t)tid * 512 + bb);
    CP_ASYNC16(sb0 + (u32)(tid + 256) * 16u, g_pre + (size_t)(tid + 256) * 512 + bb);
    CP_COMMIT();
    CP_WAIT0();

    int u0 = w * 16 + gid, u1 = u0 + 8;
    int b0 = tig * 2, b1 = b0 + 1;
    bool act = (tig < 2);
    float cs0 = 0.f, cs1 = 0.f, cs2 = 0.f, cs3 = 0.f;
    float hv0 = 0.f, hv1 = 0.f, hv2 = 0.f, hv3 = 0.f;
    __syncthreads();

    for (int t = 0; t < TT; t++) {
        int p = t & 1;
        const float* sp = sbuf[p];

        float acc[4][4];
        if (act) {
            #pragma unroll
            for (int gg = 0; gg < 4; gg++) {
                float2 qa = *(const float2*)(sp + (gg * 128 + u0) * 4 + b0);
                float2 qb = *(const float2*)(sp + (gg * 128 + u1) * 4 + b0);
                acc[gg][0] = qa.x; acc[gg][1] = qa.y;
                acc[gg][2] = qb.x; acc[gg][3] = qb.y;
            }
        } else {
            #pragma unroll
            for (int gg = 0; gg < 4; gg++) {
                acc[gg][0] = 0.f; acc[gg][1] = 0.f;
                acc[gg][2] = 0.f; acc[gg][3] = 0.f;
            }
        }

        if (t + 1 < TT) {
            u32 dst = (p ? sb0 : sb1);
            const float* gsrc = g_pre + (size_t)(t + 1) * G4 * 512 + bb;
            CP_ASYNC16(dst + (u32)tid * 16u, gsrc + (size_t)tid * 512);
            CP_ASYNC16(dst + (u32)(tid + 256) * 16u, gsrc + (size_t)(tid + 256) * 512);
        }
        CP_COMMIT();

        u32 bfr[8][2];
        #pragma unroll
        for (int kt = 0; kt < 8; kt++) {
            const u32* bp = (const u32*)(hB + gid * 136 + kt * 16 + tig * 2);
            bfr[kt][0] = bp[0];
            bfr[kt][1] = bp[4];
        }
        __syncthreads();

        #pragma unroll
        for (int gg = 0; gg < 4; gg++) {
            #pragma unroll
            for (int kt = 0; kt < 8; kt++)
                MMA16816(acc[gg], areg[gg][kt], bfr[kt]);
        }

        #pragma unroll
        for (int gg = 0; gg < 4; gg++) {
            #pragma unroll
            for (int i = 0; i < 4; i++)
                acc[gg][i] += __shfl_xor_sync(0xFFFFFFFFu, acc[gg][i], 2);
        }

        if (act) {
            cs0 = siga(acc[1][0]) * cs0 + siga(acc[0][0]) * tanha(acc[2][0]);
            hv0 = siga(acc[3][0]) * tanha(cs0);
            cs1 = siga(acc[1][1]) * cs1 + siga(acc[0][1]) * tanha(acc[2][1]);
            hv1 = siga(acc[3][1]) * tanha(cs1);
            cs2 = siga(acc[1][2]) * cs2 + siga(acc[0][2]) * tanha(acc[2][2]);
            hv2 = siga(acc[3][2]) * tanha(cs2);
            cs3 = siga(acc[1][3]) * cs3 + siga(acc[0][3]) * tanha(acc[2][3]);
            hv3 = siga(acc[3][3]) * tanha(cs3);

            __half h0h = __float2half_rn(hv0);
            __half h1h = __float2half_rn(hv1);
            __half h2h = __float2half_rn(hv2);
            __half h3h = __float2half_rn(hv3);
            hB[b0 * 136 + u0] = h0h;
            hB[b1 * 136 + u0] = h1h;
            hB[b0 * 136 + u1] = h2h;
            hB[b1 * 136 + u1] = h3h;
            hB[(b0 + 4) * 136 + u0] = __float2half_rn(hv0 - __half2float(h0h));
            hB[(b1 + 4) * 136 + u0] = __float2half_rn(hv1 - __half2float(h1h));
            hB[(b0 + 4) * 136 + u1] = __float2half_rn(hv2 - __half2float(h2h));
            hB[(b1 + 4) * 136 + u1] = __float2half_rn(hv3 - __half2float(h3h));
            if (write_hs) {
                g_hs0[((size_t)t * BB + bb + b0) * HH + u0] = hv0;
                g_hs0[((size_t)t * BB + bb + b1) * HH + u0] = hv1;
                g_hs0[((size_t)t * BB + bb + b0) * HH + u1] = hv2;
                g_hs0[((size_t)t * BB + bb + b1) * HH + u1] = hv3;
            }
        }
        CP_WAIT0();
        __syncthreads();
    }
    if (write_last && act) {
        g_last[(bb + b0) * HH + u0] = hv0;
        g_last[(bb + b1) * HH + u0] = hv1;
        g_last[(bb + b0) * HH + u1] = hv2;
        g_last[(bb + b1) * HH + u1] = hv3;
    }
}

// ---------------- MLP head (unchanged) ---------------------------------------
__global__ __launch_bounds__(128) void k_head(
                       const float* __restrict__ W1, const float* __restrict__ b1,
                       const float* __restrict__ W2, const float* __restrict__ b2,
                       const float* __restrict__ W3, const float* __restrict__ b3,
                       float* __restrict__ out) {
    __shared__ float xin[128], y1[128], y2[64];
    int b = blockIdx.x, j = threadIdx.x;
    xin[j] = g_last[b * HH + j];
    __syncthreads();
    float s = b1[j];
    #pragma unroll 4
    for (int k = 0; k < 128; k++) s += xin[k] * W1[j * 128 + k];
    y1[j] = fmaxf(s, 0.f);
    __syncthreads();
    if (j < 64) {
        float s2 = b2[j];
        #pragma unroll 4
        for (int k = 0; k < 128; k++) s2 += y1[k] * W2[j * 128 + k];
        y2[j] = fmaxf(s2, 0.f);
    }
    __syncthreads();
    if (j < 26) {
        float s3 = b3[j];
        #pragma unroll 4
        for (int k = 0; k < 64; k++) s3 += y2[k] * W3[j * 64 + k];
        out[b * 26 + j] = s3;
    }
}

// ---------------- launch -----------------------------------------------------
extern "C" void kernel_launch(void* const* d_in, const int* in_sizes, int n_in,
                              void* d_out, int out_size) {
    const float* xs   = (const float*)d_in[0];
    const float* xt   = (const float*)d_in[1];
    const float* Wgcn = (const float*)d_in[2];
    const float* bgcn = (const float*)d_in[3];
    const float* Wte  = (const float*)d_in[4];
    const float* bte  = (const float*)d_in[5];
    const float* Wih0 = (const float*)d_in[6];
    const float* Whh0 = (const float*)d_in[7];
    const float* bih0 = (const float*)d_in[8];
    const float* bhh0 = (const float*)d_in[9];
    const float* Wih1 = (const float*)d_in[10];
    const float* Whh1 = (const float*)d_in[11];
    const float* bih1 = (const float*)d_in[12];
    const float* bhh1 = (const float*)d_in[13];
    const float* W1   = (const float*)d_in[14];
    const float* b1   = (const float*)d_in[15];
    const float* W2   = (const float*)d_in[16];
    const float* b2   = (const float*)d_in[17];
    const float* W3   = (const float*)d_in[18];
    const float* b3   = (const float*)d_in[19];

    const int SM_PRE0 = (42 * 512 + 42 * 8) * 4;                  //  87,360 B
    const int SM_PRE1 = 65536 + 2 * 64 * P1_STRIDE * 2;           // 102,400 B
    cudaFuncSetAttribute(k_pre0, cudaFuncAttributeMaxDynamicSharedMemorySize, SM_PRE0);
    cudaFuncSetAttribute(k_pre1, cudaFuncAttributeMaxDynamicSharedMemorySize, SM_PRE1);

    k_comb<<<1, 512>>>(Wgcn, bgcn, Wte, bte, Wih0, bih0, bhh0, bih1, bhh1);
    k_pe<<<(TT * 512 + 255) / 256, 256>>>(Wih0);
    k_pre0<<<TT, 256, SM_PRE0>>>(xs, xt);
    k_lstm<<<BB / 4, 256>>>(Whh0, 1, 0);            // layer 0 -> hs0
    k_pre1<<<TT, 256, SM_PRE1>>>(Wih1);             // g_pre := pre1 (HMMA)
    k_lstm<<<BB / 4, 256>>>(Whh1, 0, 1);            // layer 1 -> last
    k_head<<<BB, 128>>>(W1, b1, W2, b2, W3, b3, (float*)d_out);
}

// round 16
// speedup vs baseline: 2.7908x; 1.3177x over previous
#include <cuda_runtime.h>
#include <cuda_fp16.h>
#include <cstdint>
#include <cstddef>
#include <math.h>

#define TT   1000
#define BB   512
#define HH   128
#define G4   512
#define KIN  208

typedef unsigned long long u64;
typedef unsigned int u32;

// ---------------- device scratch --------------------------------------------
// g_pre layout: [t][grp(128)][j(512)][4]   grp = b/4  (one lstm-CTA batch quad)
__device__ float g_pre[(size_t)TT * BB * G4];
__device__ float g_hs0[(size_t)TT * BB * HH];   // [t][b][128]
__device__ float g_Mcomb[42 * 512];
__device__ float g_bias0[512];
__device__ float g_bias1[512];
__device__ float g_peproj[TT * 512];
__device__ float g_last[BB * HH];

// ---------------- f32x2 helpers ---------------------------------------------
#define FFMA2(d, a, b, c) \
    asm("fma.rn.f32x2 %0, %1, %2, %3;" : "=l"(d) : "l"(a), "l"(b), "l"(c))
#define PACK2(d, x) \
    asm("mov.b64 %0, {%1, %1};" : "=l"(d) : "r"(__float_as_uint(x)))
#define UNPK2(lo, hi, x) \
    asm("mov.b64 {%0, %1}, %2;" : "=r"(lo), "=r"(hi) : "l"(x))

__device__ __forceinline__ float tanha(float x) {
    float y;
    asm("tanh.approx.f32 %0, %1;" : "=f"(y) : "f"(x));
    return y;
}
__device__ __forceinline__ float siga(float x) {
    return fmaf(tanha(0.5f * x), 0.5f, 0.5f);
}

// ---------------- warp-MMA / cp.async helpers --------------------------------
__device__ __forceinline__ u32 pack_h2(float a, float b) {
    __half2 h = __floats2half2_rn(a, b);
    return *(u32*)&h;
}
#define MMA16816(C, A, B) \
    asm volatile("mma.sync.aligned.m16n8k16.row.col.f32.f16.f16.f32 " \
        "{%0,%1,%2,%3}, {%4,%5,%6,%7}, {%8,%9}, {%0,%1,%2,%3};" \
        : "+f"((C)[0]), "+f"((C)[1]), "+f"((C)[2]), "+f"((C)[3]) \
        : "r"((A)[0]), "r"((A)[1]), "r"((A)[2]), "r"((A)[3]), \
          "r"((B)[0]), "r"((B)[1]))
__device__ __forceinline__ u32 smem_u32(const void* p) {
    u32 a;
    asm("{ .reg .u64 t; cvta.to.shared.u64 t, %1; cvt.u32.u64 %0, t; }" : "=r"(a) : "l"(p));
    return a;
}
#define CP_ASYNC16(saddr, gptr) \
    asm volatile("cp.async.cg.shared.global [%0], [%1], 16;" :: "r"(saddr), "l"(gptr))
#define CP_COMMIT() asm volatile("cp.async.commit_group;" ::: "memory")
#define CP_WAIT0()  asm volatile("cp.async.wait_group 0;" ::: "memory")
#define CP_WAIT1()  asm volatile("cp.async.wait_group 1;" ::: "memory")

// ---------------- weight combine (unchanged, passing) ------------------------
__global__ __launch_bounds__(512) void k_comb(
                       const float* __restrict__ Wgcn, const float* __restrict__ bgcn,
                       const float* __restrict__ Wte,  const float* __restrict__ bte,
                       const float* __restrict__ Wih0, const float* __restrict__ bih0,
                       const float* __restrict__ bhh0, const float* __restrict__ bih1,
                       const float* __restrict__ bhh1) {
    int j = threadIdx.x;
    const float* wr = Wih0 + (size_t)j * KIN;
    for (int k = 0; k < 16; k++) {
        float s = 0.f;
        #pragma unroll 4
        for (int d = 0; d < 64; d++) s += Wgcn[k * 64 + d] * (wr[d] + wr[64 + d]);
        g_Mcomb[k * 512 + j] = 0.5f * s;
    }
    for (int k = 0; k < 26; k++) {
        float s = 0.f;
        #pragma unroll 4
        for (int d = 0; d < 64; d++) s += Wte[k * 64 + d] * wr[144 + d];
        g_Mcomb[(16 + k) * 512 + j] = s;
    }
    float b0 = bih0[j] + bhh0[j];
    #pragma unroll 4
    for (int d = 0; d < 64; d++) b0 += bgcn[d] * (wr[d] + wr[64 + d]) + bte[d] * wr[144 + d];
    g_bias0[j] = b0;
    g_bias1[j] = bih1[j] + bhh1[j];
}

// ---------------- positional encoding projection (unchanged) -----------------
__global__ __launch_bounds__(256) void k_pe(const float* __restrict__ Wih0) {
    int id = blockIdx.x * blockDim.x + threadIdx.x;
    if (id >= TT * 512) return;
    int t = id >> 9, j = id & 511;
    const float* wr = Wih0 + (size_t)j * KIN + 128;
    float acc = 0.f;
    #pragma unroll
    for (int i = 0; i < 8; i++) {
        float div = expf(-(float)(2 * i) * (9.210340371976184f / 16.0f));
        float ang = (float)t * div;
        acc += sinf(ang) * wr[2 * i] + cosf(ang) * wr[2 * i + 1];
    }
    g_peproj[id] = acc;
}

// ---------------- pre0: g_pre[t][grp][j][4] = x42 @ M + pe + bias0 -----------
__global__ __launch_bounds__(256, 1) void k_pre0(const float* __restrict__ xs,
                                                 const float* __restrict__ xt) {
    extern __shared__ float sm[];
    float* Msm = sm;               // [42][512]
    float* xT  = sm + 42 * 512;    // [42][8]
    int t = blockIdx.x, tid = threadIdx.x;
    int j0 = tid * 2;
    for (int i = tid; i < 42 * 512; i += 256) Msm[i] = g_Mcomb[i];
    u64 bj0, bj1;
    PACK2(bj0, g_bias0[j0]     + g_peproj[t * 512 + j0]);
    PACK2(bj1, g_bias0[j0 + 1] + g_peproj[t * 512 + j0 + 1]);
    __syncthreads();
    for (int bt = 0; bt < 64; bt++) {
        int bb = bt * 8;
        #pragma unroll
        for (int s = 0; s < 2; s++) {
            int i = tid + s * 256;
            if (i < 128) {
                int b = i >> 4, k = i & 15;
                const float* xp = xs + ((size_t)(bb + b) * TT + t) * 32;
                xT[k * 8 + b] = xp[k] + xp[k + 16];
            } else if (i < 336) {
                int idx = i - 128; int b = idx / 26, k = idx - b * 26;
                xT[(16 + k) * 8 + b] = xt[((size_t)(bb + b) * TT + t) * 26 + k];
            }
        }
        __syncthreads();
        u64 A[8];
        A[0] = bj0; A[1] = bj0; A[2] = bj0; A[3] = bj0;
        A[4] = bj1; A[5] = bj1; A[6] = bj1; A[7] = bj1;
        #pragma unroll 6
        for (int k = 0; k < 42; k++) {
            float2 w = *(const float2*)(Msm + k * 512 + j0);
            u64 wa, wb; PACK2(wa, w.x); PACK2(wb, w.y);
            ulonglong2 h0 = *(const ulonglong2*)(xT + k * 8);
            ulonglong2 h1 = *(const ulonglong2*)(xT + k * 8 + 4);
            FFMA2(A[0], wa, h0.x, A[0]); FFMA2(A[1], wa, h0.y, A[1]);
            FFMA2(A[2], wa, h1.x, A[2]); FFMA2(A[3], wa, h1.y, A[3]);
            FFMA2(A[4], wb, h0.x, A[4]); FFMA2(A[5], wb, h0.y, A[5]);
            FFMA2(A[6], wb, h1.x, A[6]); FFMA2(A[7], wb, h1.y, A[7]);
        }
        unsigned zj0[8], zj1[8];
        UNPK2(zj0[0], zj0[1], A[0]); UNPK2(zj0[2], zj0[3], A[1]);
        UNPK2(zj0[4], zj0[5], A[2]); UNPK2(zj0[6], zj0[7], A[3]);
        UNPK2(zj1[0], zj1[1], A[4]); UNPK2(zj1[2], zj1[3], A[5]);
        UNPK2(zj1[4], zj1[5], A[6]); UNPK2(zj1[6], zj1[7], A[7]);
        // store: groups g0 = bt*2 (b 0-3), g1 = bt*2+1 (b 4-7); [t][g][j][4]
        size_t base = ((size_t)t * 128 + bt * 2) * 2048;
        *(float4*)(g_pre + base + (size_t)j0 * 4) = make_float4(
            __uint_as_float(zj0[0]), __uint_as_float(zj0[1]),
            __uint_as_float(zj0[2]), __uint_as_float(zj0[3]));
        *(float4*)(g_pre + base + (size_t)(j0 + 1) * 4) = make_float4(
            __uint_as_float(zj1[0]), __uint_as_float(zj1[1]),
            __uint_as_float(zj1[2]), __uint_as_float(zj1[3]));
        *(float4*)(g_pre + base + 2048 + (size_t)j0 * 4) = make_float4(
            __uint_as_float(zj0[4]), __uint_as_float(zj0[5]),
            __uint_as_float(zj0[6]), __uint_as_float(zj0[7]));
        *(float4*)(g_pre + base + 2048 + (size_t)(j0 + 1) * 4) = make_float4(
            __uint_as_float(zj1[4]), __uint_as_float(zj1[5]),
            __uint_as_float(zj1[6]), __uint_as_float(zj1[7]));
        __syncthreads();
    }
}

// ---------------- pre1 via warp HMMA (stores updated to [t][grp][j][4]) ------
#define P1_STRIDE 144
__global__ __launch_bounds__(256, 1) void k_pre1(const float* __restrict__ Wih1) {
    extern __shared__ char smp[];
    float*  stage  = (float*)smp;                       // [2][64*128] = 64 KB
    __half* planeH = (__half*)(smp + 65536);            // [64][144]
    __half* planeL = planeH + 64 * P1_STRIDE;           // [64][144]
    u32 stage_s = smem_u32(stage);

    int t = blockIdx.x, tid = threadIdx.x;
    int w = tid >> 5, lane = tid & 31;
    int gid = lane >> 2, tig = lane & 3;
    bool act = (tig < 2);

    u32 areg[4][8][4];
    float bias[8];
    #pragma unroll
    for (int gg = 0; gg < 4; gg++) {
        int r0 = (w + 8 * gg) * 16 + gid;
        const float* W0 = Wih1 + (size_t)r0 * HH;
        const float* W1 = Wih1 + (size_t)(r0 + 8) * HH;
        #pragma unroll
        for (int kt = 0; kt < 8; kt++) {
            int cc = kt * 16 + tig * 2;
            areg[gg][kt][0] = pack_h2(W0[cc], W0[cc + 1]);
            areg[gg][kt][1] = pack_h2(W1[cc], W1[cc + 1]);
            areg[gg][kt][2] = pack_h2(W0[cc + 8], W0[cc + 9]);
            areg[gg][kt][3] = pack_h2(W1[cc + 8], W1[cc + 9]);
        }
        bias[gg * 2]     = g_bias1[r0];
        bias[gg * 2 + 1] = g_bias1[r0 + 8];
    }

    {
        const float* src = g_hs0 + (size_t)t * BB * HH;
        #pragma unroll
        for (int i = 0; i < 8; i++)
            CP_ASYNC16(stage_s + (u32)(tid + i * 256) * 16u, src + (tid + i * 256) * 4);
        CP_COMMIT();
    }

    for (int c = 0; c < 8; c++) {
        if (c < 7) {
            const float* src = g_hs0 + ((size_t)t * BB + (c + 1) * 64) * HH;
            u32 dst = stage_s + (u32)((c + 1) & 1) * 32768u;
            #pragma unroll
            for (int i = 0; i < 8; i++)
                CP_ASYNC16(dst + (u32)(tid + i * 256) * 16u, src + (tid + i * 256) * 4);
            CP_COMMIT();
            CP_WAIT1();
        } else {
            CP_WAIT0();
        }
        __syncthreads();
        const float* st = stage + (c & 1) * 8192;
        #pragma unroll
        for (int i = 0; i < 8; i++) {
            int idx4 = tid + i * 256;
            float4 v = *(const float4*)(st + (size_t)idx4 * 4);
            int row = idx4 >> 5;
            int col = (idx4 & 31) * 4;
            __half h0 = __float2half_rn(v.x), h1 = __float2half_rn(v.y);
            __half h2 = __float2half_rn(v.z), h3 = __float2half_rn(v.w);
            __half l0 = __float2half_rn(v.x - __half2float(h0));
            __half l1 = __float2half_rn(v.y - __half2float(h1));
            __half l2 = __float2half_rn(v.z - __half2float(h2));
            __half l3 = __float2half_rn(v.w - __half2float(h3));
            __half2* ph = (__half2*)(planeH + row * P1_STRIDE + col);
            __half2* pl = (__half2*)(planeL + row * P1_STRIDE + col);
            ph[0] = __halves2half2(h0, h1); ph[1] = __halves2half2(h2, h3);
            pl[0] = __halves2half2(l0, l1); pl[1] = __halves2half2(l2, l3);
        }
        __syncthreads();

        const __half* pb = ((gid < 4) ? planeH : planeL) + (gid & 3) * P1_STRIDE;
        for (int grp = 0; grp < 16; grp++) {
            float acc[4][4];
            #pragma unroll
            for (int gg = 0; gg < 4; gg++) {
                float b0v = act ? bias[gg * 2] : 0.f;
                float b1v = act ? bias[gg * 2 + 1] : 0.f;
                acc[gg][0] = b0v; acc[gg][1] = b0v;
                acc[gg][2] = b1v; acc[gg][3] = b1v;
            }
            const __half* pr = pb + grp * 4 * P1_STRIDE;
            u32 bfr[8][2];
            #pragma unroll
            for (int kt = 0; kt < 8; kt++) {
                bfr[kt][0] = *(const u32*)(pr + kt * 16 + tig * 2);
                bfr[kt][1] = *(const u32*)(pr + kt * 16 + tig * 2 + 8);
            }
            #pragma unroll
            for (int gg = 0; gg < 4; gg++) {
                #pragma unroll
                for (int kt = 0; kt < 8; kt++)
                    MMA16816(acc[gg], areg[gg][kt], bfr[kt]);
            }
            #pragma unroll
            for (int gg = 0; gg < 4; gg++) {
                #pragma unroll
                for (int i = 0; i < 4; i++)
                    acc[gg][i] += __shfl_xor_sync(0xFFFFFFFFu, acc[gg][i], 2);
            }
            if (act) {
                // batch group index = c*16 + grp; lane offset within quad = tig*2
                size_t base = ((size_t)t * 128 + c * 16 + grp) * 2048 + tig * 2;
                #pragma unroll
                for (int gg = 0; gg < 4; gg++) {
                    int j0 = (w + 8 * gg) * 16 + gid;
                    *(float2*)(g_pre + base + (size_t)j0 * 4) =
                        make_float2(acc[gg][0], acc[gg][1]);
                    *(float2*)(g_pre + base + (size_t)(j0 + 8) * 4) =
                        make_float2(acc[gg][2], acc[gg][3]);
                }
            }
        }
        __syncthreads();
    }
}

// ---------------- LSTM sweep: warp HMMA + contiguous cp.async prefetch -------
__global__ __launch_bounds__(256, 1)
void k_lstm(const float* __restrict__ Whh, int write_hs, int write_last) {
    __shared__ __half hB[8 * 136];
    __shared__ __align__(16) float sbuf[2][2048];   // [p][j(512)][4]
    int tid  = threadIdx.x;
    int w    = tid >> 5;
    int lane = tid & 31;
    int gid  = lane >> 2;
    int tig  = lane & 3;
    int bb   = blockIdx.x * 4;

    u32 areg[4][8][4];
    #pragma unroll
    for (int gg = 0; gg < 4; gg++) {
        int r0 = (w + 8 * gg) * 16 + gid;
        const float* W0 = Whh + (size_t)r0 * HH;
        const float* W1 = Whh + (size_t)(r0 + 8) * HH;
        #pragma unroll
        for (int kt = 0; kt < 8; kt++) {
            int cc = kt * 16 + tig * 2;
            areg[gg][kt][0] = pack_h2(W0[cc], W0[cc + 1]);
            areg[gg][kt][1] = pack_h2(W1[cc], W1[cc + 1]);
            areg[gg][kt][2] = pack_h2(W0[cc + 8], W0[cc + 9]);
            areg[gg][kt][3] = pack_h2(W1[cc + 8], W1[cc + 9]);
        }
    }
    for (int i = tid; i < 8 * 136; i += 256) hB[i] = __float2half(0.f);

    u32 sb0 = smem_u32(&sbuf[0][0]);
    u32 sb1 = smem_u32(&sbuf[1][0]);
    // preload step 0: contiguous 8KB slab for this CTA's batch quad
    {
        const float* gsrc = g_pre + (size_t)blockIdx.x * 2048;
        CP_ASYNC16(sb0 + (u32)tid * 16u, gsrc + (size_t)tid * 4);
        CP_ASYNC16(sb0 + (u32)(tid + 256) * 16u, gsrc + (size_t)(tid + 256) * 4);
        CP_COMMIT();
        CP_WAIT0();
    }

    int u0 = w * 16 + gid, u1 = u0 + 8;
    int b0 = tig * 2, b1 = b0 + 1;
    bool act = (tig < 2);
    float cs0 = 0.f, cs1 = 0.f, cs2 = 0.f, cs3 = 0.f;
    float hv0 = 0.f, hv1 = 0.f, hv2 = 0.f, hv3 = 0.f;
    __syncthreads();

    for (int t = 0; t < TT; t++) {
        int p = t & 1;
        const float* sp = sbuf[p];

        float acc[4][4];
        if (act) {
            #pragma unroll
            for (int gg = 0; gg < 4; gg++) {
                float2 qa = *(const float2*)(sp + (gg * 128 + u0) * 4 + b0);
                float2 qb = *(const float2*)(sp + (gg * 128 + u1) * 4 + b0);
                acc[gg][0] = qa.x; acc[gg][1] = qa.y;
                acc[gg][2] = qb.x; acc[gg][3] = qb.y;
            }
        } else {
            #pragma unroll
            for (int gg = 0; gg < 4; gg++) {
                acc[gg][0] = 0.f; acc[gg][1] = 0.f;
                acc[gg][2] = 0.f; acc[gg][3] = 0.f;
            }
        }

        if (t + 1 < TT) {
            u32 dst = (p ? sb0 : sb1);
            const float* gsrc = g_pre + ((size_t)(t + 1) * 128 + blockIdx.x) * 2048;
            CP_ASYNC16(dst + (u32)tid * 16u, gsrc + (size_t)tid * 4);
            CP_ASYNC16(dst + (u32)(tid + 256) * 16u, gsrc + (size_t)(tid + 256) * 4);
        }
        CP_COMMIT();

        u32 bfr[8][2];
        #pragma unroll
        for (int kt = 0; kt < 8; kt++) {
            const u32* bp = (const u32*)(hB + gid * 136 + kt * 16 + tig * 2);
            bfr[kt][0] = bp[0];
            bfr[kt][1] = bp[4];
        }
        __syncthreads();

        #pragma unroll
        for (int gg = 0; gg < 4; gg++) {
            #pragma unroll
            for (int kt = 0; kt < 8; kt++)
                MMA16816(acc[gg], areg[gg][kt], bfr[kt]);
        }

        #pragma unroll
        for (int gg = 0; gg < 4; gg++) {
            #pragma unroll
            for (int i = 0; i < 4; i++)
                acc[gg][i] += __shfl_xor_sync(0xFFFFFFFFu, acc[gg][i], 2);
        }

        if (act) {
            cs0 = siga(acc[1][0]) * cs0 + siga(acc[0][0]) * tanha(acc[2][0]);
            hv0 = siga(acc[3][0]) * tanha(cs0);
            cs1 = siga(acc[1][1]) * cs1 + siga(acc[0][1]) * tanha(acc[2][1]);
            hv1 = siga(acc[3][1]) * tanha(cs1);
            cs2 = siga(acc[1][2]) * cs2 + siga(acc[0][2]) * tanha(acc[2][2]);
            hv2 = siga(acc[3][2]) * tanha(cs2);
            cs3 = siga(acc[1][3]) * cs3 + siga(acc[0][3]) * tanha(acc[2][3]);
            hv3 = siga(acc[3][3]) * tanha(cs3);

            __half h0h = __float2half_rn(hv0);
            __half h1h = __float2half_rn(hv1);
            __half h2h = __float2half_rn(hv2);
            __half h3h = __float2half_rn(hv3);
            hB[b0 * 136 + u0] = h0h;
            hB[b1 * 136 + u0] = h1h;
            hB[b0 * 136 + u1] = h2h;
            hB[b1 * 136 + u1] = h3h;
            hB[(b0 + 4) * 136 + u0] = __float2half_rn(hv0 - __half2float(h0h));
            hB[(b1 + 4) * 136 + u0] = __float2half_rn(hv1 - __half2float(h1h));
            hB[(b0 + 4) * 136 + u1] = __float2half_rn(hv2 - __half2float(h2h));
            hB[(b1 + 4) * 136 + u1] = __float2half_rn(hv3 - __half2float(h3h));
            if (write_hs) {
                g_hs0[((size_t)t * BB + bb + b0) * HH + u0] = hv0;
                g_hs0[((size_t)t * BB + bb + b1) * HH + u0] = hv1;
                g_hs0[((size_t)t * BB + bb + b0) * HH + u1] = hv2;
                g_hs0[((size_t)t * BB + bb + b1) * HH + u1] = hv3;
            }
        }
        CP_WAIT0();
        __syncthreads();
    }
    if (write_last && act) {
        g_last[(bb + b0) * HH + u0] = hv0;
        g_last[(bb + b1) * HH + u0] = hv1;
        g_last[(bb + b0) * HH + u1] = hv2;
        g_last[(bb + b1) * HH + u1] = hv3;
    }
}

// ---------------- MLP head (unchanged) ---------------------------------------
__global__ __launch_bounds__(128) void k_head(
                       const float* __restrict__ W1, const float* __restrict__ b1,
                       const float* __restrict__ W2, const float* __restrict__ b2,
                       const float* __restrict__ W3, const float* __restrict__ b3,
                       float* __restrict__ out) {
    __shared__ float xin[128], y1[128], y2[64];
    int b = blockIdx.x, j = threadIdx.x;
    xin[j] = g_last[b * HH + j];
    __syncthreads();
    float s = b1[j];
    #pragma unroll 4
    for (int k = 0; k < 128; k++) s += xin[k] * W1[j * 128 + k];
    y1[j] = fmaxf(s, 0.f);
    __syncthreads();
    if (j < 64) {
        float s2 = b2[j];
        #pragma unroll 4
        for (int k = 0; k < 128; k++) s2 += y1[k] * W2[j * 128 + k];
        y2[j] = fmaxf(s2, 0.f);
    }
    __syncthreads();
    if (j < 26) {
        float s3 = b3[j];
        #pragma unroll 4
        for (int k = 0; k < 64; k++) s3 += y2[k] * W3[j * 64 + k];
        out[b * 26 + j] = s3;
    }
}

// ---------------- launch -----------------------------------------------------
extern "C" void kernel_launch(void* const* d_in, const int* in_sizes, int n_in,
                              void* d_out, int out_size) {
    const float* xs   = (const float*)d_in[0];
    const float* xt   = (const float*)d_in[1];
    const float* Wgcn = (const float*)d_in[2];
    const float* bgcn = (const float*)d_in[3];
    const float* Wte  = (const float*)d_in[4];
    const float* bte  = (const float*)d_in[5];
    const float* Wih0 = (const float*)d_in[6];
    const float* Whh0 = (const float*)d_in[7];
    const float* bih0 = (const float*)d_in[8];
    const float* bhh0 = (const float*)d_in[9];
    const float* Wih1 = (const float*)d_in[10];
    const float* Whh1 = (const float*)d_in[11];
    const float* bih1 = (const float*)d_in[12];
    const float* bhh1 = (const float*)d_in[13];
    const float* W1   = (const float*)d_in[14];
    const float* b1   = (const float*)d_in[15];
    const float* W2   = (const float*)d_in[16];
    const float* b2   = (const float*)d_in[17];
    const float* W3   = (const float*)d_in[18];
    const float* b3   = (const float*)d_in[19];

    const int SM_PRE0 = (42 * 512 + 42 * 8) * 4;                  //  87,360 B
    const int SM_PRE1 = 65536 + 2 * 64 * P1_STRIDE * 2;           // 102,400 B
    cudaFuncSetAttribute(k_pre0, cudaFuncAttributeMaxDynamicSharedMemorySize, SM_PRE0);
    cudaFuncSetAttribute(k_pre1, cudaFuncAttributeMaxDynamicSharedMemorySize, SM_PRE1);

    k_comb<<<1, 512>>>(Wgcn, bgcn, Wte, bte, Wih0, bih0, bhh0, bih1, bhh1);
    k_pe<<<(TT * 512 + 255) / 256, 256>>>(Wih0);
    k_pre0<<<TT, 256, SM_PRE0>>>(xs, xt);
    k_lstm<<<BB / 4, 256>>>(Whh0, 1, 0);            // layer 0 -> hs0
    k_pre1<<<TT, 256, SM_PRE1>>>(Wih1);             // g_pre := pre1 (HMMA)
    k_lstm<<<BB / 4, 256>>>(Whh1, 0, 1);            // layer 1 -> last
    k_head<<<BB, 128>>>(W1, b1, W2, b2, W3, b3, (float*)d_out);
}

// round 17
// speedup vs baseline: 3.0261x; 1.0843x over previous
#include <cuda_runtime.h>
#include <cuda_fp16.h>
#include <cstdint>
#include <cstddef>
#include <math.h>

#define TT   1000
#define BB   512
#define HH   128
#define G4   512
#define KIN  208

typedef unsigned long long u64;
typedef unsigned int u32;

// ---------------- device scratch --------------------------------------------
// g_pre layout: [t][grp(128)][j(512)][4]   grp = b/4  (one lstm-CTA batch quad)
__device__ float g_pre[(size_t)TT * BB * G4];
__device__ float g_hs0[(size_t)TT * BB * HH];   // [t][b][128]
__device__ float g_Mcomb[42 * 512];             // [k][j]
__device__ float g_bias0[512];
__device__ float g_bias1[512];
__device__ float g_peproj[TT * 512];
__device__ float g_last[BB * HH];

__device__ __forceinline__ float tanha(float x) {
    float y;
    asm("tanh.approx.f32 %0, %1;" : "=f"(y) : "f"(x));
    return y;
}
__device__ __forceinline__ float siga(float x) {
    return fmaf(tanha(0.5f * x), 0.5f, 0.5f);
}

// ---------------- warp-MMA / cp.async helpers --------------------------------
__device__ __forceinline__ u32 pack_h2(float a, float b) {
    __half2 h = __floats2half2_rn(a, b);
    return *(u32*)&h;
}
#define MMA16816(C, A, B) \
    asm volatile("mma.sync.aligned.m16n8k16.row.col.f32.f16.f16.f32 " \
        "{%0,%1,%2,%3}, {%4,%5,%6,%7}, {%8,%9}, {%0,%1,%2,%3};" \
        : "+f"((C)[0]), "+f"((C)[1]), "+f"((C)[2]), "+f"((C)[3]) \
        : "r"((A)[0]), "r"((A)[1]), "r"((A)[2]), "r"((A)[3]), \
          "r"((B)[0]), "r"((B)[1]))
__device__ __forceinline__ u32 smem_u32(const void* p) {
    u32 a;
    asm("{ .reg .u64 t; cvta.to.shared.u64 t, %1; cvt.u32.u64 %0, t; }" : "=r"(a) : "l"(p));
    return a;
}
#define CP_ASYNC16(saddr, gptr) \
    asm volatile("cp.async.cg.shared.global [%0], [%1], 16;" :: "r"(saddr), "l"(gptr))
#define CP_COMMIT() asm volatile("cp.async.commit_group;" ::: "memory")
#define CP_WAIT0()  asm volatile("cp.async.wait_group 0;" ::: "memory")
#define CP_WAIT1()  asm volatile("cp.async.wait_group 1;" ::: "memory")

// ---------------- weight combine (unchanged, passing) ------------------------
__global__ __launch_bounds__(512) void k_comb(
                       const float* __restrict__ Wgcn, const float* __restrict__ bgcn,
                       const float* __restrict__ Wte,  const float* __restrict__ bte,
                       const float* __restrict__ Wih0, const float* __restrict__ bih0,
                       const float* __restrict__ bhh0, const float* __restrict__ bih1,
                       const float* __restrict__ bhh1) {
    int j = threadIdx.x;
    const float* wr = Wih0 + (size_t)j * KIN;
    for (int k = 0; k < 16; k++) {
        float s = 0.f;
        #pragma unroll 4
        for (int d = 0; d < 64; d++) s += Wgcn[k * 64 + d] * (wr[d] + wr[64 + d]);
        g_Mcomb[k * 512 + j] = 0.5f * s;
    }
    for (int k = 0; k < 26; k++) {
        float s = 0.f;
        #pragma unroll 4
        for (int d = 0; d < 64; d++) s += Wte[k * 64 + d] * wr[144 + d];
        g_Mcomb[(16 + k) * 512 + j] = s;
    }
    float b0 = bih0[j] + bhh0[j];
    #pragma unroll 4
    for (int d = 0; d < 64; d++) b0 += bgcn[d] * (wr[d] + wr[64 + d]) + bte[d] * wr[144 + d];
    g_bias0[j] = b0;
    g_bias1[j] = bih1[j] + bhh1[j];
}

// ---------------- positional encoding projection (unchanged) -----------------
__global__ __launch_bounds__(256) void k_pe(const float* __restrict__ Wih0) {
    int id = blockIdx.x * blockDim.x + threadIdx.x;
    if (id >= TT * 512) return;
    int t = id >> 9, j = id & 511;
    const float* wr = Wih0 + (size_t)j * KIN + 128;
    float acc = 0.f;
    #pragma unroll
    for (int i = 0; i < 8; i++) {
        float div = expf(-(float)(2 * i) * (9.210340371976184f / 16.0f));
        float ang = (float)t * div;
        acc += sinf(ang) * wr[2 * i] + cosf(ang) * wr[2 * i + 1];
    }
    g_peproj[id] = acc;
}

// ---------------- pre0 via warp HMMA -----------------------------------------
// One CTA per t. out[j=512][b=512] = Mcomb^T[j][k48] @ x42[b][k] + bias0 + pe.
// Same fragment scheme as pre1; K=48 (3 k-tiles). x hi/lo-split planes.
#define P0_STRIDE 56
__global__ __launch_bounds__(256, 1) void k_pre0(const float* __restrict__ xs,
                                                 const float* __restrict__ xt) {
    __shared__ __align__(16) __half planeH[64 * P0_STRIDE];
    __shared__ __align__(16) __half planeL[64 * P0_STRIDE];
    int t = blockIdx.x, tid = threadIdx.x;
    int w = tid >> 5, lane = tid & 31;
    int gid = lane >> 2, tig = lane & 3;
    bool act = (tig < 2);

    // A fragments from Mcomb [k][j] (A[j][k] = Mcomb[k][j]); pad k 42..47 -> 0
    u32 areg[4][3][4];
    float seed[8];
    #pragma unroll
    for (int gg = 0; gg < 4; gg++) {
        int r0 = (w + 8 * gg) * 16 + gid;
        #pragma unroll
        for (int kt = 0; kt < 3; kt++) {
            int cc = kt * 16 + tig * 2;
            float m00 = (cc < 42)     ? g_Mcomb[cc * 512 + r0]           : 0.f;
            float m01 = (cc + 1 < 42) ? g_Mcomb[(cc + 1) * 512 + r0]     : 0.f;
            float m10 = (cc < 42)     ? g_Mcomb[cc * 512 + r0 + 8]       : 0.f;
            float m11 = (cc + 1 < 42) ? g_Mcomb[(cc + 1) * 512 + r0 + 8] : 0.f;
            float m02 = (cc + 8 < 42) ? g_Mcomb[(cc + 8) * 512 + r0]     : 0.f;
            float m03 = (cc + 9 < 42) ? g_Mcomb[(cc + 9) * 512 + r0]     : 0.f;
            float m12 = (cc + 8 < 42) ? g_Mcomb[(cc + 8) * 512 + r0 + 8] : 0.f;
            float m13 = (cc + 9 < 42) ? g_Mcomb[(cc + 9) * 512 + r0 + 8] : 0.f;
            areg[gg][kt][0] = pack_h2(m00, m01);
            areg[gg][kt][1] = pack_h2(m10, m11);
            areg[gg][kt][2] = pack_h2(m02, m03);
            areg[gg][kt][3] = pack_h2(m12, m13);
        }
        seed[gg * 2]     = g_bias0[r0]     + g_peproj[t * 512 + r0];
        seed[gg * 2 + 1] = g_bias0[r0 + 8] + g_peproj[t * 512 + r0 + 8];
    }

    for (int c = 0; c < 8; c++) {
        __syncthreads();                  // planes free (previous MMA reads done)
        // gather x42 for batches [c*64, c*64+64) into hi/lo planes
        #pragma unroll
        for (int i = tid; i < 64 * 16; i += 256) {
            int r = i >> 4, k = i & 15;
            const float* xp = xs + ((size_t)(c * 64 + r) * TT + t) * 32;
            float v = xp[k] + xp[k + 16];
            __half h = __float2half_rn(v);
            planeH[r * P0_STRIDE + k] = h;
            planeL[r * P0_STRIDE + k] = __float2half_rn(v - __half2float(h));
        }
        for (int i = tid; i < 64 * 26; i += 256) {
            int r = i / 26, k = i - r * 26;
            float v = xt[((size_t)(c * 64 + r) * TT + t) * 26 + k];
            __half h = __float2half_rn(v);
            planeH[r * P0_STRIDE + 16 + k] = h;
            planeL[r * P0_STRIDE + 16 + k] = __float2half_rn(v - __half2float(h));
        }
        for (int i = tid; i < 64 * 6; i += 256) {
            int r = i / 6, k = 42 + (i - r * 6);
            planeH[r * P0_STRIDE + k] = __float2half(0.f);
            planeL[r * P0_STRIDE + k] = __float2half(0.f);
        }
        __syncthreads();

        const __half* pb = ((gid < 4) ? planeH : planeL) + (gid & 3) * P0_STRIDE;
        for (int grp = 0; grp < 16; grp++) {
            float acc[4][4];
            #pragma unroll
            for (int gg = 0; gg < 4; gg++) {
                float s0 = act ? seed[gg * 2] : 0.f;
                float s1 = act ? seed[gg * 2 + 1] : 0.f;
                acc[gg][0] = s0; acc[gg][1] = s0;
                acc[gg][2] = s1; acc[gg][3] = s1;
            }
            const __half* pr = pb + grp * 4 * P0_STRIDE;
            u32 bfr[3][2];
            #pragma unroll
            for (int kt = 0; kt < 3; kt++) {
                bfr[kt][0] = *(const u32*)(pr + kt * 16 + tig * 2);
                bfr[kt][1] = *(const u32*)(pr + kt * 16 + tig * 2 + 8);
            }
            #pragma unroll
            for (int gg = 0; gg < 4; gg++) {
                #pragma unroll
                for (int kt = 0; kt < 3; kt++)
                    MMA16816(acc[gg], areg[gg][kt], bfr[kt]);
            }
            #pragma unroll
            for (int gg = 0; gg < 4; gg++) {
                #pragma unroll
                for (int i = 0; i < 4; i++)
                    acc[gg][i] += __shfl_xor_sync(0xFFFFFFFFu, acc[gg][i], 2);
            }
            if (act) {
                size_t base = ((size_t)t * 128 + c * 16 + grp) * 2048 + tig * 2;
                #pragma unroll
                for (int gg = 0; gg < 4; gg++) {
                    int j0 = (w + 8 * gg) * 16 + gid;
                    *(float2*)(g_pre + base + (size_t)j0 * 4) =
                        make_float2(acc[gg][0], acc[gg][1]);
                    *(float2*)(g_pre + base + (size_t)(j0 + 8) * 4) =
                        make_float2(acc[gg][2], acc[gg][3]);
                }
            }
        }
    }
}

// ---------------- pre1 via warp HMMA (unchanged from R16, passing) -----------
#define P1_STRIDE 144
__global__ __launch_bounds__(256, 1) void k_pre1(const float* __restrict__ Wih1) {
    extern __shared__ char smp[];
    float*  stage  = (float*)smp;                       // [2][64*128] = 64 KB
    __half* planeH = (__half*)(smp + 65536);            // [64][144]
    __half* planeL = planeH + 64 * P1_STRIDE;           // [64][144]
    u32 stage_s = smem_u32(stage);

    int t = blockIdx.x, tid = threadIdx.x;
    int w = tid >> 5, lane = tid & 31;
    int gid = lane >> 2, tig = lane & 3;
    bool act = (tig < 2);

    u32 areg[4][8][4];
    float bias[8];
    #pragma unroll
    for (int gg = 0; gg < 4; gg++) {
        int r0 = (w + 8 * gg) * 16 + gid;
        const float* W0 = Wih1 + (size_t)r0 * HH;
        const float* W1 = Wih1 + (size_t)(r0 + 8) * HH;
        #pragma unroll
        for (int kt = 0; kt < 8; kt++) {
            int cc = kt * 16 + tig * 2;
            areg[gg][kt][0] = pack_h2(W0[cc], W0[cc + 1]);
            areg[gg][kt][1] = pack_h2(W1[cc], W1[cc + 1]);
            areg[gg][kt][2] = pack_h2(W0[cc + 8], W0[cc + 9]);
            areg[gg][kt][3] = pack_h2(W1[cc + 8], W1[cc + 9]);
        }
        bias[gg * 2]     = g_bias1[r0];
        bias[gg * 2 + 1] = g_bias1[r0 + 8];
    }

    {
        const float* src = g_hs0 + (size_t)t * BB * HH;
        #pragma unroll
        for (int i = 0; i < 8; i++)
            CP_ASYNC16(stage_s + (u32)(tid + i * 256) * 16u, src + (tid + i * 256) * 4);
        CP_COMMIT();
    }

    for (int c = 0; c < 8; c++) {
        if (c < 7) {
            const float* src = g_hs0 + ((size_t)t * BB + (c + 1) * 64) * HH;
            u32 dst = stage_s + (u32)((c + 1) & 1) * 32768u;
            #pragma unroll
            for (int i = 0; i < 8; i++)
                CP_ASYNC16(dst + (u32)(tid + i * 256) * 16u, src + (tid + i * 256) * 4);
            CP_COMMIT();
            CP_WAIT1();
        } else {
            CP_WAIT0();
        }
        __syncthreads();
        const float* st = stage + (c & 1) * 8192;
        #pragma unroll
        for (int i = 0; i < 8; i++) {
            int idx4 = tid + i * 256;
            float4 v = *(const float4*)(st + (size_t)idx4 * 4);
            int row = idx4 >> 5;
            int col = (idx4 & 31) * 4;
            __half h0 = __float2half_rn(v.x), h1 = __float2half_rn(v.y);
            __half h2 = __float2half_rn(v.z), h3 = __float2half_rn(v.w);
            __half l0 = __float2half_rn(v.x - __half2float(h0));
            __half l1 = __float2half_rn(v.y - __half2float(h1));
            __half l2 = __float2half_rn(v.z - __half2float(h2));
            __half l3 = __float2half_rn(v.w - __half2float(h3));
            __half2* ph = (__half2*)(planeH + row * P1_STRIDE + col);
            __half2* pl = (__half2*)(planeL + row * P1_STRIDE + col);
            ph[0] = __halves2half2(h0, h1); ph[1] = __halves2half2(h2, h3);
            pl[0] = __halves2half2(l0, l1); pl[1] = __halves2half2(l2, l3);
        }
        __syncthreads();

        const __half* pb = ((gid < 4) ? planeH : planeL) + (gid & 3) * P1_STRIDE;
        for (int grp = 0; grp < 16; grp++) {
            float acc[4][4];
            #pragma unroll
            for (int gg = 0; gg < 4; gg++) {
                float b0v = act ? bias[gg * 2] : 0.f;
                float b1v = act ? bias[gg * 2 + 1] : 0.f;
                acc[gg][0] = b0v; acc[gg][1] = b0v;
                acc[gg][2] = b1v; acc[gg][3] = b1v;
            }
            const __half* pr = pb + grp * 4 * P1_STRIDE;
            u32 bfr[8][2];
            #pragma unroll
            for (int kt = 0; kt < 8; kt++) {
                bfr[kt][0] = *(const u32*)(pr + kt * 16 + tig * 2);
                bfr[kt][1] = *(const u32*)(pr + kt * 16 + tig * 2 + 8);
            }
            #pragma unroll
            for (int gg = 0; gg < 4; gg++) {
                #pragma unroll
                for (int kt = 0; kt < 8; kt++)
                    MMA16816(acc[gg], areg[gg][kt], bfr[kt]);
            }
            #pragma unroll
            for (int gg = 0; gg < 4; gg++) {
                #pragma unroll
                for (int i = 0; i < 4; i++)
                    acc[gg][i] += __shfl_xor_sync(0xFFFFFFFFu, acc[gg][i], 2);
            }
            if (act) {
                size_t base = ((size_t)t * 128 + c * 16 + grp) * 2048 + tig * 2;
                #pragma unroll
                for (int gg = 0; gg < 4; gg++) {
                    int j0 = (w + 8 * gg) * 16 + gid;
                    *(float2*)(g_pre + base + (size_t)j0 * 4) =
                        make_float2(acc[gg][0], acc[gg][1]);
                    *(float2*)(g_pre + base + (size_t)(j0 + 8) * 4) =
                        make_float2(acc[gg][2], acc[gg][3]);
                }
            }
        }
        __syncthreads();
    }
}

// ---------------- LSTM sweep: HMMA + slab prefetch + double-buffered hB ------
// One barrier per step: iter t reads hB[t&1], writes hB[(t+1)&1]; the end-of-
// iter barrier orders both hazards (prior-iter reads finished behind it).
__global__ __launch_bounds__(256, 1)
void k_lstm(const float* __restrict__ Whh, int write_hs, int write_last) {
    __shared__ __half hB[2][8 * 136];
    __shared__ __align__(16) float sbuf[2][2048];   // [p][j(512)][4]
    int tid  = threadIdx.x;
    int w    = tid >> 5;
    int lane = tid & 31;
    int gid  = lane >> 2;
    int tig  = lane & 3;
    int bb   = blockIdx.x * 4;

    u32 areg[4][8][4];
    #pragma unroll
    for (int gg = 0; gg < 4; gg++) {
        int r0 = (w + 8 * gg) * 16 + gid;
        const float* W0 = Whh + (size_t)r0 * HH;
        const float* W1 = Whh + (size_t)(r0 + 8) * HH;
        #pragma unroll
        for (int kt = 0; kt < 8; kt++) {
            int cc = kt * 16 + tig * 2;
            areg[gg][kt][0] = pack_h2(W0[cc], W0[cc + 1]);
            areg[gg][kt][1] = pack_h2(W1[cc], W1[cc + 1]);
            areg[gg][kt][2] = pack_h2(W0[cc + 8], W0[cc + 9]);
            areg[gg][kt][3] = pack_h2(W1[cc + 8], W1[cc + 9]);
        }
    }
    for (int i = tid; i < 2 * 8 * 136; i += 256) hB[0][i] = __float2half(0.f);

    u32 sb0 = smem_u32(&sbuf[0][0]);
    u32 sb1 = smem_u32(&sbuf[1][0]);
    {
        const float* gsrc = g_pre + (size_t)blockIdx.x * 2048;
        CP_ASYNC16(sb0 + (u32)tid * 16u, gsrc + (size_t)tid * 4);
        CP_ASYNC16(sb0 + (u32)(tid + 256) * 16u, gsrc + (size_t)(tid + 256) * 4);
        CP_COMMIT();
        CP_WAIT0();
    }

    int u0 = w * 16 + gid, u1 = u0 + 8;
    int b0 = tig * 2, b1 = b0 + 1;
    bool act = (tig < 2);
    float cs0 = 0.f, cs1 = 0.f, cs2 = 0.f, cs3 = 0.f;
    float hv0 = 0.f, hv1 = 0.f, hv2 = 0.f, hv3 = 0.f;
    __syncthreads();

    for (int t = 0; t < TT; t++) {
        int p = t & 1;
        const float* sp = sbuf[p];
        const __half* hRd = hB[p];
        __half* hWr = hB[p ^ 1];

        float acc[4][4];
        if (act) {
            #pragma unroll
            for (int gg = 0; gg < 4; gg++) {
                float2 qa = *(const float2*)(sp + (gg * 128 + u0) * 4 + b0);
                float2 qb = *(const float2*)(sp + (gg * 128 + u1) * 4 + b0);
                acc[gg][0] = qa.x; acc[gg][1] = qa.y;
                acc[gg][2] = qb.x; acc[gg][3] = qb.y;
            }
        } else {
            #pragma unroll
            for (int gg = 0; gg < 4; gg++) {
                acc[gg][0] = 0.f; acc[gg][1] = 0.f;
                acc[gg][2] = 0.f; acc[gg][3] = 0.f;
            }
        }

        if (t + 1 < TT) {
            u32 dst = (p ? sb0 : sb1);
            const float* gsrc = g_pre + ((size_t)(t + 1) * 128 + blockIdx.x) * 2048;
            CP_ASYNC16(dst + (u32)tid * 16u, gsrc + (size_t)tid * 4);
            CP_ASYNC16(dst + (u32)(tid + 256) * 16u, gsrc + (size_t)(tid + 256) * 4);
        }
        CP_COMMIT();

        u32 bfr[8][2];
        #pragma unroll
        for (int kt = 0; kt < 8; kt++) {
            const u32* bp = (const u32*)(hRd + gid * 136 + kt * 16 + tig * 2);
            bfr[kt][0] = bp[0];
            bfr[kt][1] = bp[4];
        }

        #pragma unroll
        for (int gg = 0; gg < 4; gg++) {
            #pragma unroll
            for (int kt = 0; kt < 8; kt++)
                MMA16816(acc[gg], areg[gg][kt], bfr[kt]);
        }

        #pragma unroll
        for (int gg = 0; gg < 4; gg++) {
            #pragma unroll
            for (int i = 0; i < 4; i++)
                acc[gg][i] += __shfl_xor_sync(0xFFFFFFFFu, acc[gg][i], 2);
        }

        if (act) {
            cs0 = siga(acc[1][0]) * cs0 + siga(acc[0][0]) * tanha(acc[2][0]);
            hv0 = siga(acc[3][0]) * tanha(cs0);
            cs1 = siga(acc[1][1]) * cs1 + siga(acc[0][1]) * tanha(acc[2][1]);
            hv1 = siga(acc[3][1]) * tanha(cs1);
            cs2 = siga(acc[1][2]) * cs2 + siga(acc[0][2]) * tanha(acc[2][2]);
            hv2 = siga(acc[3][2]) * tanha(cs2);
            cs3 = siga(acc[1][3]) * cs3 + siga(acc[0][3]) * tanha(acc[2][3]);
            hv3 = siga(acc[3][3]) * tanha(cs3);

            __half h0h = __float2half_rn(hv0);
            __half h1h = __float2half_rn(hv1);
            __half h2h = __float2half_rn(hv2);
            __half h3h = __float2half_rn(hv3);
            hWr[b0 * 136 + u0] = h0h;
            hWr[b1 * 136 + u0] = h1h;
            hWr[b0 * 136 + u1] = h2h;
            hWr[b1 * 136 + u1] = h3h;
            hWr[(b0 + 4) * 136 + u0] = __float2half_rn(hv0 - __half2float(h0h));
            hWr[(b1 + 4) * 136 + u0] = __float2half_rn(hv1 - __half2float(h1h));
            hWr[(b0 + 4) * 136 + u1] = __float2half_rn(hv2 - __half2float(h2h));
            hWr[(b1 + 4) * 136 + u1] = __float2half_rn(hv3 - __half2float(h3h));
            if (write_hs) {
                g_hs0[((size_t)t * BB + bb + b0) * HH + u0] = hv0;
                g_hs0[((size_t)t * BB + bb + b1) * HH + u0] = hv1;
                g_hs0[((size_t)t * BB + bb + b0) * HH + u1] = hv2;
                g_hs0[((size_t)t * BB + bb + b1) * HH + u1] = hv3;
            }
        }
        CP_WAIT0();
        __syncthreads();
    }
    if (write_last && act) {
        g_last[(bb + b0) * HH + u0] = hv0;
        g_last[(bb + b1) * HH + u0] = hv1;
        g_last[(bb + b0) * HH + u1] = hv2;
        g_last[(bb + b1) * HH + u1] = hv3;
    }
}

// ---------------- MLP head (unchanged) ---------------------------------------
__global__ __launch_bounds__(128) void k_head(
                       const float* __restrict__ W1, const float* __restrict__ b1,
                       const float* __restrict__ W2, const float* __restrict__ b2,
                       const float* __restrict__ W3, const float* __restrict__ b3,
                       float* __restrict__ out) {
    __shared__ float xin[128], y1[128], y2[64];
    int b = blockIdx.x, j = threadIdx.x;
    xin[j] = g_last[b * HH + j];
    __syncthreads();
    float s = b1[j];
    #pragma unroll 4
    for (int k = 0; k < 128; k++) s += xin[k] * W1[j * 128 + k];
    y1[j] = fmaxf(s, 0.f);
    __syncthreads();
    if (j < 64) {
        float s2 = b2[j];
        #pragma unroll 4
        for (int k = 0; k < 128; k++) s2 += y1[k] * W2[j * 128 + k];
        y2[j] = fmaxf(s2, 0.f);
    }
    __syncthreads();
    if (j < 26) {
        float s3 = b3[j];
        #pragma unroll 4
        for (int k = 0; k < 64; k++) s3 += y2[k] * W3[j * 64 + k];
        out[b * 26 + j] = s3;
    }
}

// ---------------- launch -----------------------------------------------------
extern "C" void kernel_launch(void* const* d_in, const int* in_sizes, int n_in,
                              void* d_out, int out_size) {
    const float* xs   = (const float*)d_in[0];
    const float* xt   = (const float*)d_in[1];
    const float* Wgcn = (const float*)d_in[2];
    const float* bgcn = (const float*)d_in[3];
    const float* Wte  = (const float*)d_in[4];
    const float* bte  = (const float*)d_in[5];
    const float* Wih0 = (const float*)d_in[6];
    const float* Whh0 = (const float*)d_in[7];
    const float* bih0 = (const float*)d_in[8];
    const float* bhh0 = (const float*)d_in[9];
    const float* Wih1 = (const float*)d_in[10];
    const float* Whh1 = (const float*)d_in[11];
    const float* bih1 = (const float*)d_in[12];
    const float* bhh1 = (const float*)d_in[13];
    const float* W1   = (const float*)d_in[14];
    const float* b1   = (const float*)d_in[15];
    const float* W2   = (const float*)d_in[16];
    const float* b2   = (const float*)d_in[17];
    const float* W3   = (const float*)d_in[18];
    const float* b3   = (const float*)d_in[19];

    const int SM_PRE1 = 65536 + 2 * 64 * P1_STRIDE * 2;           // 102,400 B
    cudaFuncSetAttribute(k_pre1, cudaFuncAttributeMaxDynamicSharedMemorySize, SM_PRE1);

    k_comb<<<1, 512>>>(Wgcn, bgcn, Wte, bte, Wih0, bih0, bhh0, bih1, bhh1);
    k_pe<<<(TT * 512 + 255) / 256, 256>>>(Wih0);
    k_pre0<<<TT, 256>>>(xs, xt);
    k_lstm<<<BB / 4, 256>>>(Whh0, 1, 0);            // layer 0 -> hs0
    k_pre1<<<TT, 256, SM_PRE1>>>(Wih1);             // g_pre := pre1 (HMMA)
    k_lstm<<<BB / 4, 256>>>(Whh1, 0, 1);            // layer 1 -> last
    k_head<<<BB, 128>>>(W1, b1, W2, b2, W3, b3, (float*)d_out);
}